// round 13
// baseline (speedup 1.0000x reference)
#include <cuda_runtime.h>
#include <cuda_bf16.h>
#include <math.h>
#include <stdint.h>

#define B_ 8
#define L_ 2048
#define E_ 512
#define D_ 64
#define HW 4096
#define STEPS_ 5

typedef unsigned long long u64;

// ---------------- packed fp32x2 (FFMA2) helpers ----------------
__device__ __forceinline__ u64 dup2(float x) {
    u64 r; asm("mov.b64 %0, {%1, %1};" : "=l"(r) : "f"(x)); return r;
}
__device__ __forceinline__ void fma2(u64& d, u64 a, u64 b) {
    asm("fma.rn.f32x2 %0, %1, %2, %0;" : "+l"(d) : "l"(a), "l"(b));
}
__device__ __forceinline__ float2 f2u(u64 v) {
    float2 f; asm("mov.b64 {%0, %1}, %2;" : "=f"(f.x), "=f"(f.y) : "l"(v)); return f;
}

// ---------------- smem / mma helpers ----------------
__device__ __forceinline__ uint32_t smem_u32(const void* p) {
    uint32_t a;
    asm("{ .reg .u64 t; cvta.to.shared.u64 t, %1; cvt.u32.u64 %0, t; }"
        : "=r"(a) : "l"(p));
    return a;
}
__device__ __forceinline__ void sts32w(uint32_t a, uint32_t v) {
    asm volatile("st.shared.b32 [%0], %1;" :: "r"(a), "r"(v));
}
__device__ __forceinline__ void sts16(uint32_t a, unsigned short v) {
    asm volatile("st.shared.b16 [%0], %1;" :: "r"(a), "h"(v));
}
__device__ __forceinline__ void ldsm_x4(uint32_t* r, uint32_t addr) {
    asm volatile("ldmatrix.sync.aligned.m8n8.x4.shared.b16 {%0,%1,%2,%3}, [%4];"
        : "=r"(r[0]), "=r"(r[1]), "=r"(r[2]), "=r"(r[3]) : "r"(addr));
}
__device__ __forceinline__ void ldsm_x2(uint32_t* r, uint32_t addr) {
    asm volatile("ldmatrix.sync.aligned.m8n8.x2.shared.b16 {%0,%1}, [%2];"
        : "=r"(r[0]), "=r"(r[1]) : "r"(addr));
}
__device__ __forceinline__ uint32_t lm_a_addr(uint32_t sbase, int mrow, int k0,
                                              int ST, int lane) {
    return sbase + (uint32_t)((mrow + (lane & 15)) * ST + k0 + ((lane >> 4) << 3)) * 2;
}
__device__ __forceinline__ uint32_t lm_b_addr(uint32_t sbase, int nrow, int k0,
                                              int ST, int lane) {
    return sbase + (uint32_t)((nrow + (lane & 7)) * ST + k0 + (((lane >> 3) & 1) << 3)) * 2;
}
__device__ __forceinline__ void mma_bf16(float* d, const uint32_t* a,
                                         uint32_t b0, uint32_t b1) {
    asm volatile(
        "mma.sync.aligned.m16n8k16.row.col.f32.bf16.bf16.f32 "
        "{%0,%1,%2,%3}, {%4,%5,%6,%7}, {%8,%9}, {%0,%1,%2,%3};"
        : "+f"(d[0]), "+f"(d[1]), "+f"(d[2]), "+f"(d[3])
        : "r"(a[0]), "r"(a[1]), "r"(a[2]), "r"(a[3]), "r"(b0), "r"(b1));
}
__device__ __forceinline__ void split2(float a0, float a1, uint32_t& hi, uint32_t& lo) {
    __nv_bfloat162 h = __floats2bfloat162_rn(a0, a1);
    float r0 = a0 - __bfloat162float(h.x);
    float r1 = a1 - __bfloat162float(h.y);
    __nv_bfloat162 l = __floats2bfloat162_rn(r0, r1);
    hi = *reinterpret_cast<uint32_t*>(&h);
    lo = *reinterpret_cast<uint32_t*>(&l);
}

// ---------------- scratch (device globals) ----------------
__device__ float g_gyi[B_*L_*64];
__device__ float g_gyiT[B_*64*L_];   // transposed: [(b*64+h)][l]
__device__ float g_gxi[B_*L_*64];
__device__ float g_gyo[B_*L_*64];
__device__ float g_gxo[B_*L_*64];
__device__ float g_proj[B_*L_*D_];
__device__ float g_field[B_*D_*HW];
__device__ float g_field2[B_*D_*HW];
__device__ float g_sampled[B_*L_*D_];
__device__ __align__(16) __nv_bfloat16 g_w1h[128*576];
__device__ __align__(16) __nv_bfloat16 g_w1l[128*576];
__device__ __align__(16) __nv_bfloat16 g_w2h[64*128];
__device__ __align__(16) __nv_bfloat16 g_w2l[64*128];

// ---------------- K-1: pre-split weights to bf16 hi/lo ----------------
__global__ void k_split_w(const float* __restrict__ w1, const float* __restrict__ w2) {
    int i = blockIdx.x * 256 + threadIdx.x;
    if (i < 128*576) {
        float v = w1[i];
        __nv_bfloat16 h = __float2bfloat16(v);
        g_w1h[i] = h;
        g_w1l[i] = __float2bfloat16(v - __bfloat162float(h));
    }
    if (i < 64*128) {
        float v = w2[i];
        __nv_bfloat16 h = __float2bfloat16(v);
        g_w2h[i] = h;
        g_w2l[i] = __float2bfloat16(v - __bfloat162float(h));
    }
}

// ---------------- K0: separable gaussians ----------------
__global__ void k_gauss(const float* __restrict__ pos,
                        const float* __restrict__ log_sigma) {
    int bl = blockIdx.x;
    int t  = threadIdx.x;
    float ls = *log_sigma;
    float si = log1pf(expf(ls)) + 1e-6f;
    float so = 2.0f * si;
    float i2si = 1.0f / (2.0f * si * si);
    float i2so = 1.0f / (2.0f * so * so);
    float py = pos[bl*2+0], px = pos[bl*2+1];
    float d  = (float)t;
    float dy2 = (d - py) * (d - py);
    float dx2 = (d - px) * (d - px);
    float gy  = expf(-dy2 * i2si);
    float gx  = expf(-dx2 * i2si);
    float gyo = expf(-dy2 * i2so);
    float gxo = expf(-dx2 * i2so);
    __shared__ float red[4][64];
    __shared__ float sums[4];
    red[0][t]=gy; red[1][t]=gx; red[2][t]=gyo; red[3][t]=gxo;
    __syncthreads();
    if (t < 4) {
        float s = 0.0f;
        #pragma unroll
        for (int i = 0; i < 64; i++) s += red[t][i];
        sums[t] = s;
    }
    __syncthreads();
    float inv_ni = 1.0f / (sums[0]*sums[1] + 1e-6f);
    float inv_no = 1.0f / (sums[2]*sums[3] + 1e-6f);
    int base = bl*64 + t;
    float gyn = gy * inv_ni;
    g_gyi[base] = gyn;
    g_gxi[base] = gx;
    g_gyo[base] = gyo * inv_no;
    g_gxo[base] = gxo;
    int b = bl >> 11, l = bl & 2047;
    g_gyiT[((size_t)(b*64) + t)*L_ + l] = gyn;
}

// ---------------- K1: proj (FFMA2) ----------------
__global__ void __launch_bounds__(256)
k_proj(const float* __restrict__ tokens, const float* __restrict__ Wt) {
    __shared__ float As[32][132];
    __shared__ float Bs[32][68];
    int m0 = blockIdx.x * 128;
    int tx = threadIdx.x;
    int m_base = (tx >> 4) * 8;
    int n_base = (tx & 15) * 4;
    u64 acc[4][4] = {};
    for (int k0 = 0; k0 < 512; k0 += 32) {
        for (int i = tx; i < 32*128; i += 256) {
            int e = i & 31, m = i >> 5;
            As[e][m] = tokens[(m0+m)*512 + k0 + e];
        }
        for (int i = tx; i < 32*64; i += 256) {
            int e = i & 31, dch = i >> 5;
            Bs[e][dch] = Wt[dch*512 + k0 + e];
        }
        __syncthreads();
        #pragma unroll 4
        for (int kk = 0; kk < 32; kk++) {
            ulonglong2 a01 = *(const ulonglong2*)&As[kk][m_base];
            ulonglong2 a23 = *(const ulonglong2*)&As[kk][m_base+4];
            u64 ap[4] = {a01.x, a01.y, a23.x, a23.y};
            float4 bv = *(const float4*)&Bs[kk][n_base];
            u64 bd[4] = {dup2(bv.x), dup2(bv.y), dup2(bv.z), dup2(bv.w)};
            #pragma unroll
            for (int p = 0; p < 4; p++)
                #pragma unroll
                for (int j = 0; j < 4; j++)
                    fma2(acc[p][j], ap[p], bd[j]);
        }
        __syncthreads();
    }
    #pragma unroll
    for (int p = 0; p < 4; p++) {
        float2 q0 = f2u(acc[p][0]), q1 = f2u(acc[p][1]);
        float2 q2 = f2u(acc[p][2]), q3 = f2u(acc[p][3]);
        int m = m0 + m_base + 2*p;
        *(float4*)&g_proj[(size_t)m*64 + n_base]     = make_float4(q0.x,q1.x,q2.x,q3.x);
        *(float4*)&g_proj[(size_t)(m+1)*64 + n_base] = make_float4(q0.y,q1.y,q2.y,q3.y);
    }
}

// ------- K2: scatter (1-row tiles). D[px=64][c=64], K=2048, 64 chunks -------
#define SC_ST 40
#define SC_AH 0
#define SC_AL 5120
#define SC_BH 10240
#define SC_BL 15360
#define SC_GX 20480
#define SC_SMEM (SC_GX + 32*65*4)

__global__ void __launch_bounds__(256) k_scatter() {
    __shared__ __align__(16) char smem[SC_SMEM];
    uint32_t sb = smem_u32(smem);
    int b  = blockIdx.y;
    int h0 = blockIdx.x;            // one h row
    int n0 = h0 * 64;
    int tx = threadIdx.x;
    int lane = tx & 31, w = tx >> 5;
    int gid = lane >> 2, tig = lane & 3;
    int mw = (w & 3) * 16;          // px
    int nw = (w >> 2) * 32;         // c
    float acc[4][4];
    #pragma unroll
    for (int c = 0; c < 4; c++)
        #pragma unroll
        for (int d = 0; d < 4; d++) acc[c][d] = 0.0f;

    float* gxs = reinterpret_cast<float*>(smem + SC_GX);   // [32][65] = gy*gx

    for (int ch = 0; ch < 64; ch++) {
        int l0 = ch * 32;
        // coalesced staging: gy-folded gx slab, plus B
        #pragma unroll
        for (int j = 0; j < 8; j++) {
            int i = tx + j * 256;
            int l = i >> 6, ww = i & 63;
            float gy = g_gyiT[((size_t)(b*64) + h0)*L_ + l0 + l];
            gxs[l*65 + ww] = gy * g_gxi[((size_t)(b*L_) + l0 + l)*64 + ww];
        }
        #pragma unroll
        for (int j = 0; j < 4; j++) {
            int i = tx + j * 256;
            int c = i & 63, kc = (i >> 6) * 2;
            float b0 = g_proj[((size_t)(b*L_) + l0 + kc)*64 + c];
            float b1 = g_proj[((size_t)(b*L_) + l0 + kc + 1)*64 + c];
            uint32_t hi, lo; split2(b0, b1, hi, lo);
            uint32_t off = (uint32_t)(c * SC_ST + kc) * 2;
            sts32w(sb + SC_BH + off, hi);
            sts32w(sb + SC_BL + off, lo);
        }
        __syncthreads();
        // build A[px][l] from smem (transpose of gxs)
        {
            int lp = (tx & 15) * 2;
            int pg = tx >> 4;
            #pragma unroll
            for (int i = 0; i < 4; i++) {
                int px = pg * 4 + i;
                float v0 = gxs[lp*65 + px];
                float v1 = gxs[(lp+1)*65 + px];
                uint32_t hi, lo; split2(v0, v1, hi, lo);
                uint32_t off = (uint32_t)(px * SC_ST + lp) * 2;
                sts32w(sb + SC_AH + off, hi);
                sts32w(sb + SC_AL + off, lo);
            }
        }
        __syncthreads();
        #pragma unroll
        for (int ks = 0; ks < 2; ks++) {
            int k0 = ks * 16;
            uint32_t ah[4], al[4];
            uint32_t ad = lm_a_addr(sb + SC_AH, mw, k0, SC_ST, lane);
            ldsm_x4(ah, ad);
            ldsm_x4(al, ad + (SC_AL - SC_AH));
            #pragma unroll
            for (int nt = 0; nt < 4; nt++) {
                uint32_t bd_ = lm_b_addr(sb + SC_BH, nw + nt*8, k0, SC_ST, lane);
                uint32_t bh[2], bl[2];
                ldsm_x2(bh, bd_);
                ldsm_x2(bl, bd_ + (SC_BL - SC_BH));
                mma_bf16(acc[nt], ah, bh[0], bh[1]);
                mma_bf16(acc[nt], ah, bl[0], bl[1]);
                mma_bf16(acc[nt], al, bh[0], bh[1]);
            }
        }
        __syncthreads();
    }
    #pragma unroll
    for (int nt = 0; nt < 4; nt++) {
        float* d = acc[nt];
        int c = nw + nt*8 + tig*2;
        int r = mw + gid;
        size_t base0 = ((size_t)(b*64) + c) * HW + n0;
        size_t base1 = base0 + HW;
        g_field[base0 + r]     = d[0];
        g_field[base1 + r]     = d[1];
        g_field[base0 + r + 8] = d[2];
        g_field[base1 + r + 8] = d[3];
    }
}

// ---- K3: fused conv step, 1-row tile, mma.sync + ldmatrix ----
#define P1_ST 40
#define H_ST 136
#define SM_IH 0
#define SM_IL 5120
#define SM_WH 10240
#define SM_WL 20480
#define SM_W2H 0
#define SM_W2L 17408
#define SM_HH 34816
#define SM_HL 52224
#define STEP_SMEM 69632

__global__ void __launch_bounds__(256, 3)
k_step(const float* __restrict__ bias1, const float* __restrict__ bias2,
       int parity) {
    extern __shared__ __align__(16) char smem[];
    uint32_t sb = smem_u32(smem);
    const float* fin  = parity ? g_field2 : g_field;
    float*       fout = parity ? g_field  : g_field2;
    int b  = blockIdx.y;
    int y0 = blockIdx.x;             // one output row
    int p0 = y0 * 64;
    int tx = threadIdx.x;
    int lane = tx & 31, w = tx >> 5;
    int gid = lane >> 2, tig = lane & 3;

    // ---------------- Phase 1: conv1 (M=64px, N=128oc, K=576) ----------------
    int mw = (w & 1) * 32;
    int nw = (w >> 1) * 32;
    float acc[2][4][4];
    #pragma unroll
    for (int a = 0; a < 2; a++)
        #pragma unroll
        for (int c = 0; c < 4; c++)
            #pragma unroll
            for (int d = 0; d < 4; d++) acc[a][c][d] = 0.0f;

    for (int it = 0; it < 18; it++) {
        int kc0 = it * 32;
        #pragma unroll
        for (int j = 0; j < 8; j++) {
            int i = tx + j * 256;
            int px = i & 63, kc = i >> 6;
            int kap = kc0 + kc;
            int ici = kap / 9, tap = kap - ici * 9;
            int ky = tap / 3, kx = tap - ky * 3;
            int y = y0 + ky - 1;
            int x = px + kx - 1;
            float v = 0.0f;
            if ((unsigned)y < 64u && (unsigned)x < 64u)
                v = fin[((size_t)(b*64) + ici) * HW + y * 64 + x];
            __nv_bfloat16 h = __float2bfloat16(v);
            __nv_bfloat16 l = __float2bfloat16(v - __bfloat162float(h));
            uint32_t off = (uint32_t)(px * P1_ST + kc) * 2;
            sts16(sb + SM_IH + off, *reinterpret_cast<unsigned short*>(&h));
            sts16(sb + SM_IL + off, *reinterpret_cast<unsigned short*>(&l));
        }
        #pragma unroll
        for (int j = 0; j < 8; j++) {
            int i = tx + j * 256;
            int oc = i >> 4, kp = (i & 15) * 2;
            uint32_t vh = *(const uint32_t*)&g_w1h[oc * 576 + kc0 + kp];
            uint32_t vl = *(const uint32_t*)&g_w1l[oc * 576 + kc0 + kp];
            uint32_t off = (uint32_t)(oc * P1_ST + kp) * 2;
            sts32w(sb + SM_WH + off, vh);
            sts32w(sb + SM_WL + off, vl);
        }
        __syncthreads();
        #pragma unroll
        for (int ks = 0; ks < 2; ks++) {
            int k0 = ks * 16;
            uint32_t ah[2][4], al[2][4];
            #pragma unroll
            for (int mt = 0; mt < 2; mt++) {
                uint32_t ad = lm_a_addr(sb + SM_IH, mw + mt*16, k0, P1_ST, lane);
                ldsm_x4(ah[mt], ad);
                ldsm_x4(al[mt], ad + (SM_IL - SM_IH));
            }
            #pragma unroll
            for (int nt = 0; nt < 4; nt++) {
                uint32_t bd_ = lm_b_addr(sb + SM_WH, nw + nt*8, k0, P1_ST, lane);
                uint32_t bh[2], bl[2];
                ldsm_x2(bh, bd_);
                ldsm_x2(bl, bd_ + (SM_WL - SM_WH));
                #pragma unroll
                for (int mt = 0; mt < 2; mt++) {
                    mma_bf16(acc[mt][nt], ah[mt], bh[0], bh[1]);
                    mma_bf16(acc[mt][nt], ah[mt], bl[0], bl[1]);
                    mma_bf16(acc[mt][nt], al[mt], bh[0], bh[1]);
                }
            }
        }
        __syncthreads();
    }
    // epilogue phase1: relu + bias -> hbufT [px][oc] bf16 hi/lo
    #pragma unroll
    for (int mt = 0; mt < 2; mt++)
        #pragma unroll
        for (int nt = 0; nt < 4; nt++) {
            float* d = acc[mt][nt];
            int c = nw + nt*8 + tig*2;
            float b0f = bias1[c], b1f = bias1[c+1];
            int r1 = mw + mt*16 + gid;
            float h00 = fmaxf(d[0] + b0f, 0.f), h01 = fmaxf(d[1] + b1f, 0.f);
            float h10 = fmaxf(d[2] + b0f, 0.f), h11 = fmaxf(d[3] + b1f, 0.f);
            uint32_t hi0, lo0, hi1, lo1;
            split2(h00, h01, hi0, lo0);
            split2(h10, h11, hi1, lo1);
            uint32_t o1 = (uint32_t)(r1 * H_ST + c) * 2;
            uint32_t o2 = (uint32_t)((r1+8) * H_ST + c) * 2;
            sts32w(sb + SM_HH + o1, hi0); sts32w(sb + SM_HL + o1, lo0);
            sts32w(sb + SM_HH + o2, hi1); sts32w(sb + SM_HL + o2, lo1);
        }
    // stage W2 (overlays phase-1 staging region)
    #pragma unroll
    for (int j = 0; j < 16; j++) {
        int i = tx + j * 256;
        int c = i >> 6, hp = (i & 63) * 2;
        uint32_t vh = *(const uint32_t*)&g_w2h[c * 128 + hp];
        uint32_t vl = *(const uint32_t*)&g_w2l[c * 128 + hp];
        uint32_t off = (uint32_t)(c * H_ST + hp) * 2;
        sts32w(sb + SM_W2H + off, vh);
        sts32w(sb + SM_W2L + off, vl);
    }
    __syncthreads();

    // ---------------- Phase 2: conv2 (M=64px, N=64c, K=128) ----------------
    int mw2 = (w & 3) * 16;
    int nw2 = (w >> 2) * 32;
    float acc2[4][4];
    #pragma unroll
    for (int c = 0; c < 4; c++)
        #pragma unroll
        for (int d = 0; d < 4; d++) acc2[c][d] = 0.0f;
    #pragma unroll
    for (int ks = 0; ks < 8; ks++) {
        int k0 = ks * 16;
        uint32_t ah[4], al[4];
        uint32_t ad = lm_a_addr(sb + SM_HH, mw2, k0, H_ST, lane);
        ldsm_x4(ah, ad);
        ldsm_x4(al, ad + (SM_HL - SM_HH));
        #pragma unroll
        for (int nt = 0; nt < 4; nt++) {
            uint32_t bd_ = lm_b_addr(sb + SM_W2H, nw2 + nt*8, k0, H_ST, lane);
            uint32_t bh[2], bl[2];
            ldsm_x2(bh, bd_);
            ldsm_x2(bl, bd_ + (SM_W2L - SM_W2H));
            mma_bf16(acc2[nt], ah, bh[0], bh[1]);
            mma_bf16(acc2[nt], ah, bl[0], bl[1]);
            mma_bf16(acc2[nt], al, bh[0], bh[1]);
        }
    }
    #pragma unroll
    for (int nt = 0; nt < 4; nt++) {
        float* d = acc2[nt];
        int c = nw2 + nt*8 + tig*2;
        int r = mw2 + gid;
        float b0f = bias2[c], b1f = bias2[c+1];
        size_t base0 = ((size_t)(b*64) + c) * HW + p0;
        size_t base1 = base0 + HW;
        fout[base0 + r]     = d[0] + b0f + fin[base0 + r];
        fout[base1 + r]     = d[1] + b1f + fin[base1 + r];
        fout[base0 + r + 8] = d[2] + b0f + fin[base0 + r + 8];
        fout[base1 + r + 8] = d[3] + b1f + fin[base1 + r + 8];
    }
}

// ---- K5: gather via mma.sync + ldmatrix, coalesced staging ----
#define GA_ST 72
#define GA_AH 0
#define GA_AL 9216
#define GA_BH 18432
#define GA_BL 27648

__global__ void __launch_bounds__(256) k_gather() {
    __shared__ __align__(16) char smem[36864];
    uint32_t sb = smem_u32(smem);
    int b  = blockIdx.y;
    int l0 = blockIdx.x * 64;
    int tx = threadIdx.x;
    int lane = tx & 31, w = tx >> 5;
    int gid = lane >> 2, tig = lane & 3;
    int mw = (w & 3) * 16;
    int nw = (w >> 2) * 32;
    float acc[4][4];
    #pragma unroll
    for (int c = 0; c < 4; c++)
        #pragma unroll
        for (int d = 0; d < 4; d++) acc[c][d] = 0.0f;

    for (int h = 0; h < 64; h++) {
        #pragma unroll
        for (int j = 0; j < 8; j++) {
            int r  = w + j * 8;
            int ww = lane * 2;
            int lg = b * L_ + l0 + r;
            float gy = g_gyo[(size_t)lg*64 + h];
            float2 g = *(const float2*)&g_gxo[(size_t)lg*64 + ww];
            uint32_t hi, lo; split2(gy * g.x, gy * g.y, hi, lo);
            uint32_t off = (uint32_t)(r * GA_ST + ww) * 2;
            sts32w(sb + GA_AH + off, hi);
            sts32w(sb + GA_AL + off, lo);
        }
        #pragma unroll
        for (int j = 0; j < 8; j++) {
            int r  = w + j * 8;
            int ww = lane * 2;
            float2 g = *(const float2*)&g_field2[((size_t)(b*64) + r)*HW + h*64 + ww];
            uint32_t hi, lo; split2(g.x, g.y, hi, lo);
            uint32_t off = (uint32_t)(r * GA_ST + ww) * 2;
            sts32w(sb + GA_BH + off, hi);
            sts32w(sb + GA_BL + off, lo);
        }
        __syncthreads();
        #pragma unroll
        for (int ks = 0; ks < 4; ks++) {
            int k0 = ks * 16;
            uint32_t ah[4], al[4];
            uint32_t ad = lm_a_addr(sb + GA_AH, mw, k0, GA_ST, lane);
            ldsm_x4(ah, ad);
            ldsm_x4(al, ad + (GA_AL - GA_AH));
            #pragma unroll
            for (int nt = 0; nt < 4; nt++) {
                uint32_t bd_ = lm_b_addr(sb + GA_BH, nw + nt*8, k0, GA_ST, lane);
                uint32_t bh[2], bl[2];
                ldsm_x2(bh, bd_);
                ldsm_x2(bl, bd_ + (GA_BL - GA_BH));
                mma_bf16(acc[nt], ah, bh[0], bh[1]);
                mma_bf16(acc[nt], ah, bl[0], bl[1]);
                mma_bf16(acc[nt], al, bh[0], bh[1]);
            }
        }
        __syncthreads();
    }
    #pragma unroll
    for (int nt = 0; nt < 4; nt++) {
        float* d = acc[nt];
        int c = nw + nt*8 + tig*2;
        int r = mw + gid;
        size_t base0 = ((size_t)(b*L_) + l0 + r) * 64 + c;
        size_t base1 = ((size_t)(b*L_) + l0 + r + 8) * 64 + c;
        g_sampled[base0]     = d[0];
        g_sampled[base0 + 1] = d[1];
        g_sampled[base1]     = d[2];
        g_sampled[base1 + 1] = d[3];
    }
}

// ---- K6: tokens_out = sampled @ W_from_field^T (FFMA2) ----
__global__ void __launch_bounds__(256)
k_out(const float* __restrict__ Wf, float* __restrict__ out) {
    __shared__ float As[64][68];
    __shared__ float Bs[64][68];
    int m0 = blockIdx.x * 64;
    int e0 = blockIdx.y * 64;
    int tx = threadIdx.x;
    int m_base = (tx >> 4) * 4;
    int n_base = (tx & 15) * 4;
    u64 acc[4][2] = {};
    for (int i = tx; i < 64*64; i += 256) {
        int c = i & 63, m = i >> 6;
        As[c][m] = g_sampled[(size_t)(m0+m)*64 + c];
    }
    for (int i = tx; i < 64*64; i += 256) {
        int c = i & 63, e = i >> 6;
        Bs[c][e] = Wf[(e0+e)*64 + c];
    }
    __syncthreads();
    #pragma unroll 4
    for (int kk = 0; kk < 64; kk++) {
        float4 a = *(const float4*)&As[kk][m_base];
        u64 ad[4] = {dup2(a.x), dup2(a.y), dup2(a.z), dup2(a.w)};
        ulonglong2 bp = *(const ulonglong2*)&Bs[kk][n_base];
        u64 bn[2] = {bp.x, bp.y};
        #pragma unroll
        for (int i2 = 0; i2 < 4; i2++)
            #pragma unroll
            for (int j = 0; j < 2; j++)
                fma2(acc[i2][j], ad[i2], bn[j]);
    }
    #pragma unroll
    for (int i2 = 0; i2 < 4; i2++) {
        float2 q0 = f2u(acc[i2][0]), q1 = f2u(acc[i2][1]);
        *(float4*)&out[(size_t)(m0+m_base+i2)*512 + e0 + n_base]
            = make_float4(q0.x, q0.y, q1.x, q1.y);
    }
}

// ------------------------------ launch -----------------------------------
extern "C" void kernel_launch(void* const* d_in, const int* in_sizes, int n_in,
                              void* d_out, int out_size) {
    const float* tokens     = (const float*)d_in[0];
    const float* positions  = (const float*)d_in[1];
    const float* W_to_field = (const float*)d_in[2];
    const float* W_from_field = (const float*)d_in[3];
    const float* conv1_w    = (const float*)d_in[4];
    const float* conv1_b    = (const float*)d_in[5];
    const float* conv2_w    = (const float*)d_in[6];
    const float* conv2_b    = (const float*)d_in[7];
    const float* log_sigma  = (const float*)d_in[8];
    float* out = (float*)d_out;

    cudaFuncSetAttribute(k_step, cudaFuncAttributeMaxDynamicSharedMemorySize,
                         STEP_SMEM);

    k_split_w<<<288, 256>>>(conv1_w, conv2_w);
    k_gauss<<<B_*L_, 64>>>(positions, log_sigma);
    k_proj<<<(B_*L_)/128, 256>>>(tokens, W_to_field);
    k_scatter<<<dim3(64, B_), 256>>>();
    for (int s = 0; s < STEPS_; s++) {
        k_step<<<dim3(64, B_), 256, STEP_SMEM>>>(conv1_b, conv2_b, s & 1);
    }
    k_gather<<<dim3(32, B_), 256>>>();
    k_out<<<dim3((B_*L_)/64, 8), 256>>>(W_from_field, out);
}

// round 14
// speedup vs baseline: 1.2113x; 1.2113x over previous
#include <cuda_runtime.h>
#include <cuda_bf16.h>
#include <math.h>
#include <stdint.h>

#define B_ 8
#define L_ 2048
#define E_ 512
#define D_ 64
#define HW 4096
#define STEPS_ 5

typedef unsigned long long u64;

// ---------------- packed fp32x2 (FFMA2) helpers ----------------
__device__ __forceinline__ u64 dup2(float x) {
    u64 r; asm("mov.b64 %0, {%1, %1};" : "=l"(r) : "f"(x)); return r;
}
__device__ __forceinline__ void fma2(u64& d, u64 a, u64 b) {
    asm("fma.rn.f32x2 %0, %1, %2, %0;" : "+l"(d) : "l"(a), "l"(b));
}
__device__ __forceinline__ float2 f2u(u64 v) {
    float2 f; asm("mov.b64 {%0, %1}, %2;" : "=f"(f.x), "=f"(f.y) : "l"(v)); return f;
}

// ---------------- smem / mma helpers ----------------
__device__ __forceinline__ uint32_t smem_u32(const void* p) {
    uint32_t a;
    asm("{ .reg .u64 t; cvta.to.shared.u64 t, %1; cvt.u32.u64 %0, t; }"
        : "=r"(a) : "l"(p));
    return a;
}
__device__ __forceinline__ void sts32w(uint32_t a, uint32_t v) {
    asm volatile("st.shared.b32 [%0], %1;" :: "r"(a), "r"(v));
}
__device__ __forceinline__ void ldsm_x4(uint32_t* r, uint32_t addr) {
    asm volatile("ldmatrix.sync.aligned.m8n8.x4.shared.b16 {%0,%1,%2,%3}, [%4];"
        : "=r"(r[0]), "=r"(r[1]), "=r"(r[2]), "=r"(r[3]) : "r"(addr));
}
__device__ __forceinline__ void ldsm_x2(uint32_t* r, uint32_t addr) {
    asm volatile("ldmatrix.sync.aligned.m8n8.x2.shared.b16 {%0,%1}, [%2];"
        : "=r"(r[0]), "=r"(r[1]) : "r"(addr));
}
__device__ __forceinline__ uint32_t lm_a_addr(uint32_t sbase, int mrow, int k0,
                                              int ST, int lane) {
    return sbase + (uint32_t)((mrow + (lane & 15)) * ST + k0 + ((lane >> 4) << 3)) * 2;
}
__device__ __forceinline__ uint32_t lm_b_addr(uint32_t sbase, int nrow, int k0,
                                              int ST, int lane) {
    return sbase + (uint32_t)((nrow + (lane & 7)) * ST + k0 + (((lane >> 3) & 1) << 3)) * 2;
}
__device__ __forceinline__ void mma_bf16(float* d, const uint32_t* a,
                                         uint32_t b0, uint32_t b1) {
    asm volatile(
        "mma.sync.aligned.m16n8k16.row.col.f32.bf16.bf16.f32 "
        "{%0,%1,%2,%3}, {%4,%5,%6,%7}, {%8,%9}, {%0,%1,%2,%3};"
        : "+f"(d[0]), "+f"(d[1]), "+f"(d[2]), "+f"(d[3])
        : "r"(a[0]), "r"(a[1]), "r"(a[2]), "r"(a[3]), "r"(b0), "r"(b1));
}
__device__ __forceinline__ void split2(float a0, float a1, uint32_t& hi, uint32_t& lo) {
    __nv_bfloat162 h = __floats2bfloat162_rn(a0, a1);
    float r0 = a0 - __bfloat162float(h.x);
    float r1 = a1 - __bfloat162float(h.y);
    __nv_bfloat162 l = __floats2bfloat162_rn(r0, r1);
    hi = *reinterpret_cast<uint32_t*>(&h);
    lo = *reinterpret_cast<uint32_t*>(&l);
}

// ---------------- scratch (device globals) ----------------
__device__ float g_gyi[B_*L_*64];
__device__ float g_gyiT[B_*64*L_];   // transposed: [(b*64+h)][l]
__device__ float g_gxi[B_*L_*64];
__device__ float g_gyo[B_*L_*64];
__device__ float g_gxo[B_*L_*64];
__device__ float g_proj[B_*L_*D_];
__device__ float g_field[B_*D_*HW];
__device__ float g_field2[B_*D_*HW];
__device__ float g_sampled[B_*L_*D_];
__device__ __align__(16) __nv_bfloat16 g_w1h[128*576];
__device__ __align__(16) __nv_bfloat16 g_w1l[128*576];
__device__ __align__(16) __nv_bfloat16 g_w2h[64*128];
__device__ __align__(16) __nv_bfloat16 g_w2l[64*128];

// ---------------- K-1: pre-split weights to bf16 hi/lo ----------------
__global__ void k_split_w(const float* __restrict__ w1, const float* __restrict__ w2) {
    int i = blockIdx.x * 256 + threadIdx.x;
    if (i < 128*576) {
        float v = w1[i];
        __nv_bfloat16 h = __float2bfloat16(v);
        g_w1h[i] = h;
        g_w1l[i] = __float2bfloat16(v - __bfloat162float(h));
    }
    if (i < 64*128) {
        float v = w2[i];
        __nv_bfloat16 h = __float2bfloat16(v);
        g_w2h[i] = h;
        g_w2l[i] = __float2bfloat16(v - __bfloat162float(h));
    }
}

// ---------------- K0: separable gaussians ----------------
__global__ void k_gauss(const float* __restrict__ pos,
                        const float* __restrict__ log_sigma) {
    int bl = blockIdx.x;
    int t  = threadIdx.x;
    float ls = *log_sigma;
    float si = log1pf(expf(ls)) + 1e-6f;
    float so = 2.0f * si;
    float i2si = 1.0f / (2.0f * si * si);
    float i2so = 1.0f / (2.0f * so * so);
    float py = pos[bl*2+0], px = pos[bl*2+1];
    float d  = (float)t;
    float dy2 = (d - py) * (d - py);
    float dx2 = (d - px) * (d - px);
    float gy  = expf(-dy2 * i2si);
    float gx  = expf(-dx2 * i2si);
    float gyo = expf(-dy2 * i2so);
    float gxo = expf(-dx2 * i2so);
    __shared__ float red[4][64];
    __shared__ float sums[4];
    red[0][t]=gy; red[1][t]=gx; red[2][t]=gyo; red[3][t]=gxo;
    __syncthreads();
    if (t < 4) {
        float s = 0.0f;
        #pragma unroll
        for (int i = 0; i < 64; i++) s += red[t][i];
        sums[t] = s;
    }
    __syncthreads();
    float inv_ni = 1.0f / (sums[0]*sums[1] + 1e-6f);
    float inv_no = 1.0f / (sums[2]*sums[3] + 1e-6f);
    int base = bl*64 + t;
    float gyn = gy * inv_ni;
    g_gyi[base] = gyn;
    g_gxi[base] = gx;
    g_gyo[base] = gyo * inv_no;
    g_gxo[base] = gxo;
    int b = bl >> 11, l = bl & 2047;
    g_gyiT[((size_t)(b*64) + t)*L_ + l] = gyn;
}

// ---------------- K1: proj (FFMA2) ----------------
__global__ void __launch_bounds__(256)
k_proj(const float* __restrict__ tokens, const float* __restrict__ Wt) {
    __shared__ float As[32][132];
    __shared__ float Bs[32][68];
    int m0 = blockIdx.x * 128;
    int tx = threadIdx.x;
    int m_base = (tx >> 4) * 8;
    int n_base = (tx & 15) * 4;
    u64 acc[4][4] = {};
    for (int k0 = 0; k0 < 512; k0 += 32) {
        for (int i = tx; i < 32*128; i += 256) {
            int e = i & 31, m = i >> 5;
            As[e][m] = tokens[(m0+m)*512 + k0 + e];
        }
        for (int i = tx; i < 32*64; i += 256) {
            int e = i & 31, dch = i >> 5;
            Bs[e][dch] = Wt[dch*512 + k0 + e];
        }
        __syncthreads();
        #pragma unroll 4
        for (int kk = 0; kk < 32; kk++) {
            ulonglong2 a01 = *(const ulonglong2*)&As[kk][m_base];
            ulonglong2 a23 = *(const ulonglong2*)&As[kk][m_base+4];
            u64 ap[4] = {a01.x, a01.y, a23.x, a23.y};
            float4 bv = *(const float4*)&Bs[kk][n_base];
            u64 bd[4] = {dup2(bv.x), dup2(bv.y), dup2(bv.z), dup2(bv.w)};
            #pragma unroll
            for (int p = 0; p < 4; p++)
                #pragma unroll
                for (int j = 0; j < 4; j++)
                    fma2(acc[p][j], ap[p], bd[j]);
        }
        __syncthreads();
    }
    #pragma unroll
    for (int p = 0; p < 4; p++) {
        float2 q0 = f2u(acc[p][0]), q1 = f2u(acc[p][1]);
        float2 q2 = f2u(acc[p][2]), q3 = f2u(acc[p][3]);
        int m = m0 + m_base + 2*p;
        *(float4*)&g_proj[(size_t)m*64 + n_base]     = make_float4(q0.x,q1.x,q2.x,q3.x);
        *(float4*)&g_proj[(size_t)(m+1)*64 + n_base] = make_float4(q0.y,q1.y,q2.y,q3.y);
    }
}

// ------- K2: scatter via mma.sync + ldmatrix, coalesced staging (R12) -------
#define SC_ST 40
#define SC_AH 0
#define SC_AL 10240
#define SC_BH 20480
#define SC_BL 25600
#define SC_GX 30720
#define SC_GY (30720 + 32*65*4)
#define SC_SMEM (SC_GY + 64*4)

__global__ void __launch_bounds__(256) k_scatter() {
    __shared__ __align__(16) char smem[SC_SMEM];
    uint32_t sb = smem_u32(smem);
    int b  = blockIdx.y;
    int n0 = blockIdx.x * 128;
    int h0 = blockIdx.x * 2;
    int tx = threadIdx.x;
    int lane = tx & 31, w = tx >> 5;
    int gid = lane >> 2, tig = lane & 3;
    int mw = (w & 3) * 32;
    int nw = (w >> 2) * 32;
    float acc[2][4][4];
    #pragma unroll
    for (int a = 0; a < 2; a++)
        #pragma unroll
        for (int c = 0; c < 4; c++)
            #pragma unroll
            for (int d = 0; d < 4; d++) acc[a][c][d] = 0.0f;

    float* gxs = reinterpret_cast<float*>(smem + SC_GX);   // [32][65]
    float* gys = reinterpret_cast<float*>(smem + SC_GY);   // [32][2]

    for (int ch = 0; ch < 64; ch++) {
        int l0 = ch * 32;
        #pragma unroll
        for (int j = 0; j < 8; j++) {
            int i = tx + j * 256;
            int l = i >> 6, ww = i & 63;
            gxs[l*65 + ww] = g_gxi[((size_t)(b*L_) + l0 + l)*64 + ww];
        }
        if (tx < 64) {
            int h = tx >> 5, l = tx & 31;
            gys[l*2 + h] = g_gyiT[((size_t)(b*64) + h0 + h)*L_ + l0 + l];
        }
        #pragma unroll
        for (int j = 0; j < 4; j++) {
            int i = tx + j * 256;
            int c = i & 63, kc = (i >> 6) * 2;
            float b0 = g_proj[((size_t)(b*L_) + l0 + kc)*64 + c];
            float b1 = g_proj[((size_t)(b*L_) + l0 + kc + 1)*64 + c];
            uint32_t hi, lo; split2(b0, b1, hi, lo);
            uint32_t off = (uint32_t)(c * SC_ST + kc) * 2;
            sts32w(sb + SC_BH + off, hi);
            sts32w(sb + SC_BL + off, lo);
        }
        __syncthreads();
        {
            int lp = (tx & 15) * 2;
            int pg = tx >> 4;
            const float* gx0r = gxs + lp * 65;
            const float* gx1r = gx0r + 65;
            float gy0a = gys[lp*2+0],     gy0b = gys[lp*2+1];
            float gy1a = gys[(lp+1)*2+0], gy1b = gys[(lp+1)*2+1];
            #pragma unroll
            for (int i = 0; i < 8; i++) {
                int px = pg * 8 + i;
                int ww = px & 63;
                float v0 = ((px < 64) ? gy0a : gy0b) * gx0r[ww];
                float v1 = ((px < 64) ? gy1a : gy1b) * gx1r[ww];
                uint32_t hi, lo; split2(v0, v1, hi, lo);
                uint32_t off = (uint32_t)(px * SC_ST + lp) * 2;
                sts32w(sb + SC_AH + off, hi);
                sts32w(sb + SC_AL + off, lo);
            }
        }
        __syncthreads();
        #pragma unroll
        for (int ks = 0; ks < 2; ks++) {
            int k0 = ks * 16;
            uint32_t ah[2][4], al[2][4];
            #pragma unroll
            for (int mt = 0; mt < 2; mt++) {
                uint32_t ad = lm_a_addr(sb + SC_AH, mw + mt*16, k0, SC_ST, lane);
                ldsm_x4(ah[mt], ad);
                ldsm_x4(al[mt], ad + (SC_AL - SC_AH));
            }
            #pragma unroll
            for (int nt = 0; nt < 4; nt++) {
                uint32_t bd_ = lm_b_addr(sb + SC_BH, nw + nt*8, k0, SC_ST, lane);
                uint32_t bh[2], bl[2];
                ldsm_x2(bh, bd_);
                ldsm_x2(bl, bd_ + (SC_BL - SC_BH));
                #pragma unroll
                for (int mt = 0; mt < 2; mt++) {
                    mma_bf16(acc[mt][nt], ah[mt], bh[0], bh[1]);
                    mma_bf16(acc[mt][nt], ah[mt], bl[0], bl[1]);
                    mma_bf16(acc[mt][nt], al[mt], bh[0], bh[1]);
                }
            }
        }
        __syncthreads();
    }
    #pragma unroll
    for (int mt = 0; mt < 2; mt++)
        #pragma unroll
        for (int nt = 0; nt < 4; nt++) {
            float* d = acc[mt][nt];
            int c  = nw + nt*8 + tig*2;
            int r1 = mw + mt*16 + gid;
            size_t base0 = ((size_t)(b*64) + c) * HW + n0;
            size_t base1 = base0 + HW;
            g_field[base0 + r1]     = d[0];
            g_field[base1 + r1]     = d[1];
            g_field[base0 + r1 + 8] = d[2];
            g_field[base1 + r1 + 8] = d[3];
        }
}

// ---- K3: fused conv step (R12 tiles) + packed im2col stores ----
#define P1_ST 40
#define H_ST 136
#define SM_IH 0
#define SM_IL 10240
#define SM_WH 20480
#define SM_WL 30720
#define SM_W2H 0
#define SM_W2L 17408
#define SM_HH 40960
#define SM_HL 75776
#define STEP_SMEM 110592

__global__ void __launch_bounds__(256, 2)
k_step(const float* __restrict__ bias1, const float* __restrict__ bias2,
       int parity) {
    extern __shared__ __align__(16) char smem[];
    uint32_t sb = smem_u32(smem);
    const float* fin  = parity ? g_field2 : g_field;
    float*       fout = parity ? g_field  : g_field2;
    int b  = blockIdx.y;
    int y0 = blockIdx.x * 2;
    int p0 = y0 * 64;
    int tx = threadIdx.x;
    int lane = tx & 31, w = tx >> 5;
    int gid = lane >> 2, tig = lane & 3;

    int mw = (w & 3) * 32;
    int nw = (w >> 2) * 64;
    float acc[2][8][4];
    #pragma unroll
    for (int a = 0; a < 2; a++)
        #pragma unroll
        for (int c = 0; c < 8; c++)
            #pragma unroll
            for (int d = 0; d < 4; d++) acc[a][c][d] = 0.0f;

    for (int it = 0; it < 18; it++) {
        int kc0 = it * 32;
        // im2col staging: kc-pairs packed into one 32-bit store per buffer
        #pragma unroll
        for (int j = 0; j < 8; j++) {
            int i = tx + j * 256;            // pair index 0..2047
            int px = i & 127;                // fastest across lanes -> coalesced
            int kp = (i >> 7) * 2;           // kc pair base 0..30
            float v0, v1;
            {
                int kap = kc0 + kp;
                int ici = kap / 9, tap = kap - ici * 9;
                int ky = tap / 3, kx = tap - ky * 3;
                int y = y0 + (px >> 6) + ky - 1;
                int x = (px & 63) + kx - 1;
                v0 = 0.0f;
                if ((unsigned)y < 64u && (unsigned)x < 64u)
                    v0 = fin[((size_t)(b*64) + ici) * HW + y * 64 + x];
            }
            {
                int kap = kc0 + kp + 1;
                int ici = kap / 9, tap = kap - ici * 9;
                int ky = tap / 3, kx = tap - ky * 3;
                int y = y0 + (px >> 6) + ky - 1;
                int x = (px & 63) + kx - 1;
                v1 = 0.0f;
                if ((unsigned)y < 64u && (unsigned)x < 64u)
                    v1 = fin[((size_t)(b*64) + ici) * HW + y * 64 + x];
            }
            uint32_t hi, lo; split2(v0, v1, hi, lo);
            uint32_t off = (uint32_t)(px * P1_ST + kp) * 2;
            sts32w(sb + SM_IH + off, hi);
            sts32w(sb + SM_IL + off, lo);
        }
        #pragma unroll
        for (int j = 0; j < 8; j++) {
            int i = tx + j * 256;
            int oc = i >> 4, kp = (i & 15) * 2;
            uint32_t vh = *(const uint32_t*)&g_w1h[oc * 576 + kc0 + kp];
            uint32_t vl = *(const uint32_t*)&g_w1l[oc * 576 + kc0 + kp];
            uint32_t off = (uint32_t)(oc * P1_ST + kp) * 2;
            sts32w(sb + SM_WH + off, vh);
            sts32w(sb + SM_WL + off, vl);
        }
        __syncthreads();
        #pragma unroll
        for (int ks = 0; ks < 2; ks++) {
            int k0 = ks * 16;
            uint32_t ah[2][4], al[2][4];
            #pragma unroll
            for (int mt = 0; mt < 2; mt++) {
                uint32_t ad = lm_a_addr(sb + SM_IH, mw + mt*16, k0, P1_ST, lane);
                ldsm_x4(ah[mt], ad);
                ldsm_x4(al[mt], ad + (SM_IL - SM_IH));
            }
            #pragma unroll
            for (int nt = 0; nt < 8; nt++) {
                uint32_t bd_ = lm_b_addr(sb + SM_WH, nw + nt*8, k0, P1_ST, lane);
                uint32_t bh[2], bl[2];
                ldsm_x2(bh, bd_);
                ldsm_x2(bl, bd_ + (SM_WL - SM_WH));
                #pragma unroll
                for (int mt = 0; mt < 2; mt++) {
                    mma_bf16(acc[mt][nt], ah[mt], bh[0], bh[1]);
                    mma_bf16(acc[mt][nt], ah[mt], bl[0], bl[1]);
                    mma_bf16(acc[mt][nt], al[mt], bh[0], bh[1]);
                }
            }
        }
        __syncthreads();
    }
    #pragma unroll
    for (int mt = 0; mt < 2; mt++)
        #pragma unroll
        for (int nt = 0; nt < 8; nt++) {
            float* d = acc[mt][nt];
            int c = nw + nt*8 + tig*2;
            float b0f = bias1[c], b1f = bias1[c+1];
            int r1 = mw + mt*16 + gid;
            float h00 = fmaxf(d[0] + b0f, 0.f), h01 = fmaxf(d[1] + b1f, 0.f);
            float h10 = fmaxf(d[2] + b0f, 0.f), h11 = fmaxf(d[3] + b1f, 0.f);
            uint32_t hi0, lo0, hi1, lo1;
            split2(h00, h01, hi0, lo0);
            split2(h10, h11, hi1, lo1);
            uint32_t o1 = (uint32_t)(r1 * H_ST + c) * 2;
            uint32_t o2 = (uint32_t)((r1+8) * H_ST + c) * 2;
            sts32w(sb + SM_HH + o1, hi0); sts32w(sb + SM_HL + o1, lo0);
            sts32w(sb + SM_HH + o2, hi1); sts32w(sb + SM_HL + o2, lo1);
        }
    #pragma unroll
    for (int j = 0; j < 16; j++) {
        int i = tx + j * 256;
        int c = i >> 6, hp = (i & 63) * 2;
        uint32_t vh = *(const uint32_t*)&g_w2h[c * 128 + hp];
        uint32_t vl = *(const uint32_t*)&g_w2l[c * 128 + hp];
        uint32_t off = (uint32_t)(c * H_ST + hp) * 2;
        sts32w(sb + SM_W2H + off, vh);
        sts32w(sb + SM_W2L + off, vl);
    }
    __syncthreads();

    int mw2 = (w & 3) * 32;
    int nw2 = (w >> 2) * 32;
    float acc2[2][4][4];
    #pragma unroll
    for (int a = 0; a < 2; a++)
        #pragma unroll
        for (int c = 0; c < 4; c++)
            #pragma unroll
            for (int d = 0; d < 4; d++) acc2[a][c][d] = 0.0f;
    #pragma unroll
    for (int ks = 0; ks < 8; ks++) {
        int k0 = ks * 16;
        uint32_t ah[2][4], al[2][4];
        #pragma unroll
        for (int mt = 0; mt < 2; mt++) {
            uint32_t ad = lm_a_addr(sb + SM_HH, mw2 + mt*16, k0, H_ST, lane);
            ldsm_x4(ah[mt], ad);
            ldsm_x4(al[mt], ad + (SM_HL - SM_HH));
        }
        #pragma unroll
        for (int nt = 0; nt < 4; nt++) {
            uint32_t bd_ = lm_b_addr(sb + SM_W2H, nw2 + nt*8, k0, H_ST, lane);
            uint32_t bh[2], bl[2];
            ldsm_x2(bh, bd_);
            ldsm_x2(bl, bd_ + (SM_W2L - SM_W2H));
            #pragma unroll
            for (int mt = 0; mt < 2; mt++) {
                mma_bf16(acc2[mt][nt], ah[mt], bh[0], bh[1]);
                mma_bf16(acc2[mt][nt], ah[mt], bl[0], bl[1]);
                mma_bf16(acc2[mt][nt], al[mt], bh[0], bh[1]);
            }
        }
    }
    #pragma unroll
    for (int mt = 0; mt < 2; mt++)
        #pragma unroll
        for (int nt = 0; nt < 4; nt++) {
            float* d = acc2[mt][nt];
            int c = nw2 + nt*8 + tig*2;
            int r1 = mw2 + mt*16 + gid;
            float b0f = bias2[c], b1f = bias2[c+1];
            size_t base0 = ((size_t)(b*64) + c) * HW + p0;
            size_t base1 = base0 + HW;
            fout[base0 + r1]     = d[0] + b0f + fin[base0 + r1];
            fout[base1 + r1]     = d[1] + b1f + fin[base1 + r1];
            fout[base0 + r1 + 8] = d[2] + b0f + fin[base0 + r1 + 8];
            fout[base1 + r1 + 8] = d[3] + b1f + fin[base1 + r1 + 8];
        }
}

// ---- K5: gather via mma.sync + ldmatrix, coalesced staging (R12) ----
#define GA_ST 72
#define GA_AH 0
#define GA_AL 9216
#define GA_BH 18432
#define GA_BL 27648

__global__ void __launch_bounds__(256) k_gather() {
    __shared__ __align__(16) char smem[36864];
    uint32_t sb = smem_u32(smem);
    int b  = blockIdx.y;
    int l0 = blockIdx.x * 64;
    int tx = threadIdx.x;
    int lane = tx & 31, w = tx >> 5;
    int gid = lane >> 2, tig = lane & 3;
    int mw = (w & 3) * 16;
    int nw = (w >> 2) * 32;
    float acc[4][4];
    #pragma unroll
    for (int c = 0; c < 4; c++)
        #pragma unroll
        for (int d = 0; d < 4; d++) acc[c][d] = 0.0f;

    for (int h = 0; h < 64; h++) {
        #pragma unroll
        for (int j = 0; j < 8; j++) {
            int r  = w + j * 8;
            int ww = lane * 2;
            int lg = b * L_ + l0 + r;
            float gy = g_gyo[(size_t)lg*64 + h];
            float2 g = *(const float2*)&g_gxo[(size_t)lg*64 + ww];
            uint32_t hi, lo; split2(gy * g.x, gy * g.y, hi, lo);
            uint32_t off = (uint32_t)(r * GA_ST + ww) * 2;
            sts32w(sb + GA_AH + off, hi);
            sts32w(sb + GA_AL + off, lo);
        }
        #pragma unroll
        for (int j = 0; j < 8; j++) {
            int r  = w + j * 8;
            int ww = lane * 2;
            float2 g = *(const float2*)&g_field2[((size_t)(b*64) + r)*HW + h*64 + ww];
            uint32_t hi, lo; split2(g.x, g.y, hi, lo);
            uint32_t off = (uint32_t)(r * GA_ST + ww) * 2;
            sts32w(sb + GA_BH + off, hi);
            sts32w(sb + GA_BL + off, lo);
        }
        __syncthreads();
        #pragma unroll
        for (int ks = 0; ks < 4; ks++) {
            int k0 = ks * 16;
            uint32_t ah[4], al[4];
            uint32_t ad = lm_a_addr(sb + GA_AH, mw, k0, GA_ST, lane);
            ldsm_x4(ah, ad);
            ldsm_x4(al, ad + (GA_AL - GA_AH));
            #pragma unroll
            for (int nt = 0; nt < 4; nt++) {
                uint32_t bd_ = lm_b_addr(sb + GA_BH, nw + nt*8, k0, GA_ST, lane);
                uint32_t bh[2], bl[2];
                ldsm_x2(bh, bd_);
                ldsm_x2(bl, bd_ + (GA_BL - GA_BH));
                mma_bf16(acc[nt], ah, bh[0], bh[1]);
                mma_bf16(acc[nt], ah, bl[0], bl[1]);
                mma_bf16(acc[nt], al, bh[0], bh[1]);
            }
        }
        __syncthreads();
    }
    #pragma unroll
    for (int nt = 0; nt < 4; nt++) {
        float* d = acc[nt];
        int c = nw + nt*8 + tig*2;
        int r = mw + gid;
        size_t base0 = ((size_t)(b*L_) + l0 + r) * 64 + c;
        size_t base1 = ((size_t)(b*L_) + l0 + r + 8) * 64 + c;
        g_sampled[base0]     = d[0];
        g_sampled[base0 + 1] = d[1];
        g_sampled[base1]     = d[2];
        g_sampled[base1 + 1] = d[3];
    }
}

// ---- K6: tokens_out = sampled @ W_from_field^T (FFMA2) ----
__global__ void __launch_bounds__(256)
k_out(const float* __restrict__ Wf, float* __restrict__ out) {
    __shared__ float As[64][68];
    __shared__ float Bs[64][68];
    int m0 = blockIdx.x * 64;
    int e0 = blockIdx.y * 64;
    int tx = threadIdx.x;
    int m_base = (tx >> 4) * 4;
    int n_base = (tx & 15) * 4;
    u64 acc[4][2] = {};
    for (int i = tx; i < 64*64; i += 256) {
        int c = i & 63, m = i >> 6;
        As[c][m] = g_sampled[(size_t)(m0+m)*64 + c];
    }
    for (int i = tx; i < 64*64; i += 256) {
        int c = i & 63, e = i >> 6;
        Bs[c][e] = Wf[(e0+e)*64 + c];
    }
    __syncthreads();
    #pragma unroll 4
    for (int kk = 0; kk < 64; kk++) {
        float4 a = *(const float4*)&As[kk][m_base];
        u64 ad[4] = {dup2(a.x), dup2(a.y), dup2(a.z), dup2(a.w)};
        ulonglong2 bp = *(const ulonglong2*)&Bs[kk][n_base];
        u64 bn[2] = {bp.x, bp.y};
        #pragma unroll
        for (int i2 = 0; i2 < 4; i2++)
            #pragma unroll
            for (int j = 0; j < 2; j++)
                fma2(acc[i2][j], ad[i2], bn[j]);
    }
    #pragma unroll
    for (int i2 = 0; i2 < 4; i2++) {
        float2 q0 = f2u(acc[i2][0]), q1 = f2u(acc[i2][1]);
        *(float4*)&out[(size_t)(m0+m_base+i2)*512 + e0 + n_base]
            = make_float4(q0.x, q0.y, q1.x, q1.y);
    }
}

// ------------------------------ launch -----------------------------------
extern "C" void kernel_launch(void* const* d_in, const int* in_sizes, int n_in,
                              void* d_out, int out_size) {
    const float* tokens     = (const float*)d_in[0];
    const float* positions  = (const float*)d_in[1];
    const float* W_to_field = (const float*)d_in[2];
    const float* W_from_field = (const float*)d_in[3];
    const float* conv1_w    = (const float*)d_in[4];
    const float* conv1_b    = (const float*)d_in[5];
    const float* conv2_w    = (const float*)d_in[6];
    const float* conv2_b    = (const float*)d_in[7];
    const float* log_sigma  = (const float*)d_in[8];
    float* out = (float*)d_out;

    cudaFuncSetAttribute(k_step, cudaFuncAttributeMaxDynamicSharedMemorySize,
                         STEP_SMEM);

    k_split_w<<<288, 256>>>(conv1_w, conv2_w);
    k_gauss<<<B_*L_, 64>>>(positions, log_sigma);
    k_proj<<<(B_*L_)/128, 256>>>(tokens, W_to_field);
    k_scatter<<<dim3(32, B_), 256>>>();
    for (int s = 0; s < STEPS_; s++) {
        k_step<<<dim3(32, B_), 256, STEP_SMEM>>>(conv1_b, conv2_b, s & 1);
    }
    k_gather<<<dim3(32, B_), 256>>>();
    k_out<<<dim3((B_*L_)/64, 8), 256>>>(W_from_field, out);
}

// round 15
// speedup vs baseline: 1.2791x; 1.0560x over previous
#include <cuda_runtime.h>
#include <cuda_bf16.h>
#include <math.h>
#include <stdint.h>

#define B_ 8
#define L_ 2048
#define E_ 512
#define D_ 64
#define HW 4096
#define STEPS_ 5

typedef unsigned long long u64;

// ---------------- packed fp32x2 (FFMA2) helpers ----------------
__device__ __forceinline__ u64 dup2(float x) {
    u64 r; asm("mov.b64 %0, {%1, %1};" : "=l"(r) : "f"(x)); return r;
}
__device__ __forceinline__ void fma2(u64& d, u64 a, u64 b) {
    asm("fma.rn.f32x2 %0, %1, %2, %0;" : "+l"(d) : "l"(a), "l"(b));
}
__device__ __forceinline__ float2 f2u(u64 v) {
    float2 f; asm("mov.b64 {%0, %1}, %2;" : "=f"(f.x), "=f"(f.y) : "l"(v)); return f;
}

// ---------------- smem / mma helpers ----------------
__device__ __forceinline__ uint32_t smem_u32(const void* p) {
    uint32_t a;
    asm("{ .reg .u64 t; cvta.to.shared.u64 t, %1; cvt.u32.u64 %0, t; }"
        : "=r"(a) : "l"(p));
    return a;
}
__device__ __forceinline__ void sts32w(uint32_t a, uint32_t v) {
    asm volatile("st.shared.b32 [%0], %1;" :: "r"(a), "r"(v));
}
__device__ __forceinline__ void ldsm_x4(uint32_t* r, uint32_t addr) {
    asm volatile("ldmatrix.sync.aligned.m8n8.x4.shared.b16 {%0,%1,%2,%3}, [%4];"
        : "=r"(r[0]), "=r"(r[1]), "=r"(r[2]), "=r"(r[3]) : "r"(addr));
}
__device__ __forceinline__ void ldsm_x2(uint32_t* r, uint32_t addr) {
    asm volatile("ldmatrix.sync.aligned.m8n8.x2.shared.b16 {%0,%1}, [%2];"
        : "=r"(r[0]), "=r"(r[1]) : "r"(addr));
}
__device__ __forceinline__ uint32_t lm_a_addr(uint32_t sbase, int mrow, int k0,
                                              int ST, int lane) {
    return sbase + (uint32_t)((mrow + (lane & 15)) * ST + k0 + ((lane >> 4) << 3)) * 2;
}
__device__ __forceinline__ uint32_t lm_b_addr(uint32_t sbase, int nrow, int k0,
                                              int ST, int lane) {
    return sbase + (uint32_t)((nrow + (lane & 7)) * ST + k0 + (((lane >> 3) & 1) << 3)) * 2;
}
__device__ __forceinline__ void mma_bf16(float* d, const uint32_t* a,
                                         uint32_t b0, uint32_t b1) {
    asm volatile(
        "mma.sync.aligned.m16n8k16.row.col.f32.bf16.bf16.f32 "
        "{%0,%1,%2,%3}, {%4,%5,%6,%7}, {%8,%9}, {%0,%1,%2,%3};"
        : "+f"(d[0]), "+f"(d[1]), "+f"(d[2]), "+f"(d[3])
        : "r"(a[0]), "r"(a[1]), "r"(a[2]), "r"(a[3]), "r"(b0), "r"(b1));
}
__device__ __forceinline__ void split2(float a0, float a1, uint32_t& hi, uint32_t& lo) {
    __nv_bfloat162 h = __floats2bfloat162_rn(a0, a1);
    float r0 = a0 - __bfloat162float(h.x);
    float r1 = a1 - __bfloat162float(h.y);
    __nv_bfloat162 l = __floats2bfloat162_rn(r0, r1);
    hi = *reinterpret_cast<uint32_t*>(&h);
    lo = *reinterpret_cast<uint32_t*>(&l);
}

// ---------------- scratch (device globals) ----------------
__device__ float g_gyi[B_*L_*64];
__device__ float g_gyiT[B_*64*L_];   // transposed: [(b*64+h)][l]
__device__ float g_gxi[B_*L_*64];
__device__ float g_gyo[B_*L_*64];
__device__ float g_gxo[B_*L_*64];
__device__ float g_proj[B_*L_*D_];
__device__ float g_field[B_*D_*HW];
__device__ float g_field2[B_*D_*HW];
__device__ float g_sampled[B_*L_*D_];
__device__ __align__(16) __nv_bfloat16 g_w1h[128*576];
__device__ __align__(16) __nv_bfloat16 g_w1l[128*576];
__device__ __align__(16) __nv_bfloat16 g_w2h[64*128];
__device__ __align__(16) __nv_bfloat16 g_w2l[64*128];

// ---------------- K-1: pre-split weights to bf16 hi/lo ----------------
__global__ void k_split_w(const float* __restrict__ w1, const float* __restrict__ w2) {
    int i = blockIdx.x * 256 + threadIdx.x;
    if (i < 128*576) {
        float v = w1[i];
        __nv_bfloat16 h = __float2bfloat16(v);
        g_w1h[i] = h;
        g_w1l[i] = __float2bfloat16(v - __bfloat162float(h));
    }
    if (i < 64*128) {
        float v = w2[i];
        __nv_bfloat16 h = __float2bfloat16(v);
        g_w2h[i] = h;
        g_w2l[i] = __float2bfloat16(v - __bfloat162float(h));
    }
}

// ---------------- K0: separable gaussians ----------------
__global__ void k_gauss(const float* __restrict__ pos,
                        const float* __restrict__ log_sigma) {
    int bl = blockIdx.x;
    int t  = threadIdx.x;
    float ls = *log_sigma;
    float si = log1pf(expf(ls)) + 1e-6f;
    float so = 2.0f * si;
    float i2si = 1.0f / (2.0f * si * si);
    float i2so = 1.0f / (2.0f * so * so);
    float py = pos[bl*2+0], px = pos[bl*2+1];
    float d  = (float)t;
    float dy2 = (d - py) * (d - py);
    float dx2 = (d - px) * (d - px);
    float gy  = expf(-dy2 * i2si);
    float gx  = expf(-dx2 * i2si);
    float gyo = expf(-dy2 * i2so);
    float gxo = expf(-dx2 * i2so);
    __shared__ float red[4][64];
    __shared__ float sums[4];
    red[0][t]=gy; red[1][t]=gx; red[2][t]=gyo; red[3][t]=gxo;
    __syncthreads();
    if (t < 4) {
        float s = 0.0f;
        #pragma unroll
        for (int i = 0; i < 64; i++) s += red[t][i];
        sums[t] = s;
    }
    __syncthreads();
    float inv_ni = 1.0f / (sums[0]*sums[1] + 1e-6f);
    float inv_no = 1.0f / (sums[2]*sums[3] + 1e-6f);
    int base = bl*64 + t;
    float gyn = gy * inv_ni;
    g_gyi[base] = gyn;
    g_gxi[base] = gx;
    g_gyo[base] = gyo * inv_no;
    g_gxo[base] = gxo;
    int b = bl >> 11, l = bl & 2047;
    g_gyiT[((size_t)(b*64) + t)*L_ + l] = gyn;
}

// ---------------- K1: proj (FFMA2) ----------------
__global__ void __launch_bounds__(256)
k_proj(const float* __restrict__ tokens, const float* __restrict__ Wt) {
    __shared__ float As[32][132];
    __shared__ float Bs[32][68];
    int m0 = blockIdx.x * 128;
    int tx = threadIdx.x;
    int m_base = (tx >> 4) * 8;
    int n_base = (tx & 15) * 4;
    u64 acc[4][4] = {};
    for (int k0 = 0; k0 < 512; k0 += 32) {
        for (int i = tx; i < 32*128; i += 256) {
            int e = i & 31, m = i >> 5;
            As[e][m] = tokens[(m0+m)*512 + k0 + e];
        }
        for (int i = tx; i < 32*64; i += 256) {
            int e = i & 31, dch = i >> 5;
            Bs[e][dch] = Wt[dch*512 + k0 + e];
        }
        __syncthreads();
        #pragma unroll 4
        for (int kk = 0; kk < 32; kk++) {
            ulonglong2 a01 = *(const ulonglong2*)&As[kk][m_base];
            ulonglong2 a23 = *(const ulonglong2*)&As[kk][m_base+4];
            u64 ap[4] = {a01.x, a01.y, a23.x, a23.y};
            float4 bv = *(const float4*)&Bs[kk][n_base];
            u64 bd[4] = {dup2(bv.x), dup2(bv.y), dup2(bv.z), dup2(bv.w)};
            #pragma unroll
            for (int p = 0; p < 4; p++)
                #pragma unroll
                for (int j = 0; j < 4; j++)
                    fma2(acc[p][j], ap[p], bd[j]);
        }
        __syncthreads();
    }
    #pragma unroll
    for (int p = 0; p < 4; p++) {
        float2 q0 = f2u(acc[p][0]), q1 = f2u(acc[p][1]);
        float2 q2 = f2u(acc[p][2]), q3 = f2u(acc[p][3]);
        int m = m0 + m_base + 2*p;
        *(float4*)&g_proj[(size_t)m*64 + n_base]     = make_float4(q0.x,q1.x,q2.x,q3.x);
        *(float4*)&g_proj[(size_t)(m+1)*64 + n_base] = make_float4(q0.y,q1.y,q2.y,q3.y);
    }
}

// ------- K2: scatter, K-chunk=64, dynamic smem -------
#define SC_ST 72
#define SC_AH 0
#define SC_AL 18432
#define SC_BH 36864
#define SC_BL 46080
#define SC_GX 55296
#define SC_GY (55296 + 64*65*4)
#define SC_SMEM (SC_GY + 128*4)

__global__ void __launch_bounds__(256) k_scatter() {
    extern __shared__ __align__(16) char smem[];
    uint32_t sb = smem_u32(smem);
    int b  = blockIdx.y;
    int n0 = blockIdx.x * 128;
    int h0 = blockIdx.x * 2;
    int tx = threadIdx.x;
    int lane = tx & 31, w = tx >> 5;
    int gid = lane >> 2, tig = lane & 3;
    int mw = (w & 3) * 32;
    int nw = (w >> 2) * 32;
    float acc[2][4][4];
    #pragma unroll
    for (int a = 0; a < 2; a++)
        #pragma unroll
        for (int c = 0; c < 4; c++)
            #pragma unroll
            for (int d = 0; d < 4; d++) acc[a][c][d] = 0.0f;

    float* gxs = reinterpret_cast<float*>(smem + SC_GX);   // [64][65]
    float* gys = reinterpret_cast<float*>(smem + SC_GY);   // [64][2]

    for (int ch = 0; ch < 32; ch++) {
        int l0 = ch * 64;
        // coalesced staging: gx slab, gy pairs, B (proj)
        #pragma unroll
        for (int j = 0; j < 16; j++) {
            int i = tx + j * 256;
            int l = i >> 6, ww = i & 63;
            gxs[l*65 + ww] = g_gxi[((size_t)(b*L_) + l0 + l)*64 + ww];
        }
        if (tx < 128) {
            int h = tx >> 6, l = tx & 63;
            gys[l*2 + h] = g_gyiT[((size_t)(b*64) + h0 + h)*L_ + l0 + l];
        }
        #pragma unroll
        for (int j = 0; j < 8; j++) {
            int i = tx + j * 256;
            int c = i & 63, kc = (i >> 6) * 2;
            float b0 = g_proj[((size_t)(b*L_) + l0 + kc)*64 + c];
            float b1 = g_proj[((size_t)(b*L_) + l0 + kc + 1)*64 + c];
            uint32_t hi, lo; split2(b0, b1, hi, lo);
            uint32_t off = (uint32_t)(c * SC_ST + kc) * 2;
            sts32w(sb + SC_BH + off, hi);
            sts32w(sb + SC_BL + off, lo);
        }
        __syncthreads();
        // build A[px][l] from smem
        {
            int lp = (lane) * 2 + (w & 1) * 64;   // no — keep simple mapping
        }
        {
            int lp = (tx & 31) * 2;     // l pair 0..62
            int pg = tx >> 5;           // 8 groups of 16 px
            const float* gx0r = gxs + lp * 65;
            const float* gx1r = gx0r + 65;
            float gy0a = gys[lp*2+0],     gy0b = gys[lp*2+1];
            float gy1a = gys[(lp+1)*2+0], gy1b = gys[(lp+1)*2+1];
            #pragma unroll
            for (int i = 0; i < 16; i++) {
                int px = pg * 16 + i;
                int ww = px & 63;
                float v0 = ((px < 64) ? gy0a : gy0b) * gx0r[ww];
                float v1 = ((px < 64) ? gy1a : gy1b) * gx1r[ww];
                uint32_t hi, lo; split2(v0, v1, hi, lo);
                uint32_t off = (uint32_t)(px * SC_ST + lp) * 2;
                sts32w(sb + SC_AH + off, hi);
                sts32w(sb + SC_AL + off, lo);
            }
        }
        __syncthreads();
        #pragma unroll
        for (int ks = 0; ks < 4; ks++) {
            int k0 = ks * 16;
            uint32_t ah[2][4], al[2][4];
            #pragma unroll
            for (int mt = 0; mt < 2; mt++) {
                uint32_t ad = lm_a_addr(sb + SC_AH, mw + mt*16, k0, SC_ST, lane);
                ldsm_x4(ah[mt], ad);
                ldsm_x4(al[mt], ad + (SC_AL - SC_AH));
            }
            #pragma unroll
            for (int nt = 0; nt < 4; nt++) {
                uint32_t bd_ = lm_b_addr(sb + SC_BH, nw + nt*8, k0, SC_ST, lane);
                uint32_t bh[2], bl[2];
                ldsm_x2(bh, bd_);
                ldsm_x2(bl, bd_ + (SC_BL - SC_BH));
                #pragma unroll
                for (int mt = 0; mt < 2; mt++) {
                    mma_bf16(acc[mt][nt], ah[mt], bh[0], bh[1]);
                    mma_bf16(acc[mt][nt], ah[mt], bl[0], bl[1]);
                    mma_bf16(acc[mt][nt], al[mt], bh[0], bh[1]);
                }
            }
        }
        __syncthreads();
    }
    #pragma unroll
    for (int mt = 0; mt < 2; mt++)
        #pragma unroll
        for (int nt = 0; nt < 4; nt++) {
            float* d = acc[mt][nt];
            int c  = nw + nt*8 + tig*2;
            int r1 = mw + mt*16 + gid;
            size_t base0 = ((size_t)(b*64) + c) * HW + n0;
            size_t base1 = base0 + HW;
            g_field[base0 + r1]     = d[0];
            g_field[base1 + r1]     = d[1];
            g_field[base0 + r1 + 8] = d[2];
            g_field[base1 + r1 + 8] = d[3];
        }
}

// ---- K3: fused conv step (R14: packed im2col stores) ----
#define P1_ST 40
#define H_ST 136
#define SM_IH 0
#define SM_IL 10240
#define SM_WH 20480
#define SM_WL 30720
#define SM_W2H 0
#define SM_W2L 17408
#define SM_HH 40960
#define SM_HL 75776
#define STEP_SMEM 110592

__global__ void __launch_bounds__(256, 2)
k_step(const float* __restrict__ bias1, const float* __restrict__ bias2,
       int parity) {
    extern __shared__ __align__(16) char smem[];
    uint32_t sb = smem_u32(smem);
    const float* fin  = parity ? g_field2 : g_field;
    float*       fout = parity ? g_field  : g_field2;
    int b  = blockIdx.y;
    int y0 = blockIdx.x * 2;
    int p0 = y0 * 64;
    int tx = threadIdx.x;
    int lane = tx & 31, w = tx >> 5;
    int gid = lane >> 2, tig = lane & 3;

    int mw = (w & 3) * 32;
    int nw = (w >> 2) * 64;
    float acc[2][8][4];
    #pragma unroll
    for (int a = 0; a < 2; a++)
        #pragma unroll
        for (int c = 0; c < 8; c++)
            #pragma unroll
            for (int d = 0; d < 4; d++) acc[a][c][d] = 0.0f;

    for (int it = 0; it < 18; it++) {
        int kc0 = it * 32;
        #pragma unroll
        for (int j = 0; j < 8; j++) {
            int i = tx + j * 256;
            int px = i & 127;
            int kp = (i >> 7) * 2;
            float v0, v1;
            {
                int kap = kc0 + kp;
                int ici = kap / 9, tap = kap - ici * 9;
                int ky = tap / 3, kx = tap - ky * 3;
                int y = y0 + (px >> 6) + ky - 1;
                int x = (px & 63) + kx - 1;
                v0 = 0.0f;
                if ((unsigned)y < 64u && (unsigned)x < 64u)
                    v0 = fin[((size_t)(b*64) + ici) * HW + y * 64 + x];
            }
            {
                int kap = kc0 + kp + 1;
                int ici = kap / 9, tap = kap - ici * 9;
                int ky = tap / 3, kx = tap - ky * 3;
                int y = y0 + (px >> 6) + ky - 1;
                int x = (px & 63) + kx - 1;
                v1 = 0.0f;
                if ((unsigned)y < 64u && (unsigned)x < 64u)
                    v1 = fin[((size_t)(b*64) + ici) * HW + y * 64 + x];
            }
            uint32_t hi, lo; split2(v0, v1, hi, lo);
            uint32_t off = (uint32_t)(px * P1_ST + kp) * 2;
            sts32w(sb + SM_IH + off, hi);
            sts32w(sb + SM_IL + off, lo);
        }
        #pragma unroll
        for (int j = 0; j < 8; j++) {
            int i = tx + j * 256;
            int oc = i >> 4, kp = (i & 15) * 2;
            uint32_t vh = *(const uint32_t*)&g_w1h[oc * 576 + kc0 + kp];
            uint32_t vl = *(const uint32_t*)&g_w1l[oc * 576 + kc0 + kp];
            uint32_t off = (uint32_t)(oc * P1_ST + kp) * 2;
            sts32w(sb + SM_WH + off, vh);
            sts32w(sb + SM_WL + off, vl);
        }
        __syncthreads();
        #pragma unroll
        for (int ks = 0; ks < 2; ks++) {
            int k0 = ks * 16;
            uint32_t ah[2][4], al[2][4];
            #pragma unroll
            for (int mt = 0; mt < 2; mt++) {
                uint32_t ad = lm_a_addr(sb + SM_IH, mw + mt*16, k0, P1_ST, lane);
                ldsm_x4(ah[mt], ad);
                ldsm_x4(al[mt], ad + (SM_IL - SM_IH));
            }
            #pragma unroll
            for (int nt = 0; nt < 8; nt++) {
                uint32_t bd_ = lm_b_addr(sb + SM_WH, nw + nt*8, k0, P1_ST, lane);
                uint32_t bh[2], bl[2];
                ldsm_x2(bh, bd_);
                ldsm_x2(bl, bd_ + (SM_WL - SM_WH));
                #pragma unroll
                for (int mt = 0; mt < 2; mt++) {
                    mma_bf16(acc[mt][nt], ah[mt], bh[0], bh[1]);
                    mma_bf16(acc[mt][nt], ah[mt], bl[0], bl[1]);
                    mma_bf16(acc[mt][nt], al[mt], bh[0], bh[1]);
                }
            }
        }
        __syncthreads();
    }
    #pragma unroll
    for (int mt = 0; mt < 2; mt++)
        #pragma unroll
        for (int nt = 0; nt < 8; nt++) {
            float* d = acc[mt][nt];
            int c = nw + nt*8 + tig*2;
            float b0f = bias1[c], b1f = bias1[c+1];
            int r1 = mw + mt*16 + gid;
            float h00 = fmaxf(d[0] + b0f, 0.f), h01 = fmaxf(d[1] + b1f, 0.f);
            float h10 = fmaxf(d[2] + b0f, 0.f), h11 = fmaxf(d[3] + b1f, 0.f);
            uint32_t hi0, lo0, hi1, lo1;
            split2(h00, h01, hi0, lo0);
            split2(h10, h11, hi1, lo1);
            uint32_t o1 = (uint32_t)(r1 * H_ST + c) * 2;
            uint32_t o2 = (uint32_t)((r1+8) * H_ST + c) * 2;
            sts32w(sb + SM_HH + o1, hi0); sts32w(sb + SM_HL + o1, lo0);
            sts32w(sb + SM_HH + o2, hi1); sts32w(sb + SM_HL + o2, lo1);
        }
    #pragma unroll
    for (int j = 0; j < 16; j++) {
        int i = tx + j * 256;
        int c = i >> 6, hp = (i & 63) * 2;
        uint32_t vh = *(const uint32_t*)&g_w2h[c * 128 + hp];
        uint32_t vl = *(const uint32_t*)&g_w2l[c * 128 + hp];
        uint32_t off = (uint32_t)(c * H_ST + hp) * 2;
        sts32w(sb + SM_W2H + off, vh);
        sts32w(sb + SM_W2L + off, vl);
    }
    __syncthreads();

    int mw2 = (w & 3) * 32;
    int nw2 = (w >> 2) * 32;
    float acc2[2][4][4];
    #pragma unroll
    for (int a = 0; a < 2; a++)
        #pragma unroll
        for (int c = 0; c < 4; c++)
            #pragma unroll
            for (int d = 0; d < 4; d++) acc2[a][c][d] = 0.0f;
    #pragma unroll
    for (int ks = 0; ks < 8; ks++) {
        int k0 = ks * 16;
        uint32_t ah[2][4], al[2][4];
        #pragma unroll
        for (int mt = 0; mt < 2; mt++) {
            uint32_t ad = lm_a_addr(sb + SM_HH, mw2 + mt*16, k0, H_ST, lane);
            ldsm_x4(ah[mt], ad);
            ldsm_x4(al[mt], ad + (SM_HL - SM_HH));
        }
        #pragma unroll
        for (int nt = 0; nt < 4; nt++) {
            uint32_t bd_ = lm_b_addr(sb + SM_W2H, nw2 + nt*8, k0, H_ST, lane);
            uint32_t bh[2], bl[2];
            ldsm_x2(bh, bd_);
            ldsm_x2(bl, bd_ + (SM_W2L - SM_W2H));
            #pragma unroll
            for (int mt = 0; mt < 2; mt++) {
                mma_bf16(acc2[mt][nt], ah[mt], bh[0], bh[1]);
                mma_bf16(acc2[mt][nt], ah[mt], bl[0], bl[1]);
                mma_bf16(acc2[mt][nt], al[mt], bh[0], bh[1]);
            }
        }
    }
    #pragma unroll
    for (int mt = 0; mt < 2; mt++)
        #pragma unroll
        for (int nt = 0; nt < 4; nt++) {
            float* d = acc2[mt][nt];
            int c = nw2 + nt*8 + tig*2;
            int r1 = mw2 + mt*16 + gid;
            float b0f = bias2[c], b1f = bias2[c+1];
            size_t base0 = ((size_t)(b*64) + c) * HW + p0;
            size_t base1 = base0 + HW;
            fout[base0 + r1]     = d[0] + b0f + fin[base0 + r1];
            fout[base1 + r1]     = d[1] + b1f + fin[base1 + r1];
            fout[base0 + r1 + 8] = d[2] + b0f + fin[base0 + r1 + 8];
            fout[base1 + r1 + 8] = d[3] + b1f + fin[base1 + r1 + 8];
        }
}

// ---- K5: gather, 2 h-rows per iteration (K=128/iter), dynamic smem ----
#define GA_ST 136
#define GA_AH 0
#define GA_AL 17408
#define GA_BH 34816
#define GA_BL 52224
#define GA_SMEM 69632

__global__ void __launch_bounds__(256) k_gather() {
    extern __shared__ __align__(16) char smem[];
    uint32_t sb = smem_u32(smem);
    int b  = blockIdx.y;
    int l0 = blockIdx.x * 64;
    int tx = threadIdx.x;
    int lane = tx & 31, w = tx >> 5;
    int gid = lane >> 2, tig = lane & 3;
    int mw = (w & 3) * 16;
    int nw = (w >> 2) * 32;
    float acc[4][4];
    #pragma unroll
    for (int c = 0; c < 4; c++)
        #pragma unroll
        for (int d = 0; d < 4; d++) acc[c][d] = 0.0f;

    for (int h2 = 0; h2 < 32; h2++) {
        int h = h2 * 2;
        // A rows: gx loaded once, reused for both h rows
        #pragma unroll
        for (int j = 0; j < 8; j++) {
            int r  = w + j * 8;
            int ww = lane * 2;
            int lg = b * L_ + l0 + r;
            float2 g = *(const float2*)&g_gxo[(size_t)lg*64 + ww];
            float gy0 = g_gyo[(size_t)lg*64 + h];
            float gy1 = g_gyo[(size_t)lg*64 + h + 1];
            uint32_t hi, lo;
            split2(gy0 * g.x, gy0 * g.y, hi, lo);
            uint32_t off = (uint32_t)(r * GA_ST + ww) * 2;
            sts32w(sb + GA_AH + off, hi);
            sts32w(sb + GA_AL + off, lo);
            split2(gy1 * g.x, gy1 * g.y, hi, lo);
            off = (uint32_t)(r * GA_ST + 64 + ww) * 2;
            sts32w(sb + GA_AH + off, hi);
            sts32w(sb + GA_AL + off, lo);
        }
        // B rows: two h rows of field2
        #pragma unroll
        for (int j = 0; j < 8; j++) {
            int r  = w + j * 8;
            int ww = lane * 2;
            const float* fr = &g_field2[((size_t)(b*64) + r)*HW + h*64];
            float2 g0 = *(const float2*)&fr[ww];
            float2 g1 = *(const float2*)&fr[64 + ww];
            uint32_t hi, lo;
            split2(g0.x, g0.y, hi, lo);
            uint32_t off = (uint32_t)(r * GA_ST + ww) * 2;
            sts32w(sb + GA_BH + off, hi);
            sts32w(sb + GA_BL + off, lo);
            split2(g1.x, g1.y, hi, lo);
            off = (uint32_t)(r * GA_ST + 64 + ww) * 2;
            sts32w(sb + GA_BH + off, hi);
            sts32w(sb + GA_BL + off, lo);
        }
        __syncthreads();
        #pragma unroll
        for (int ks = 0; ks < 8; ks++) {
            int k0 = ks * 16;
            uint32_t ah[4], al[4];
            uint32_t ad = lm_a_addr(sb + GA_AH, mw, k0, GA_ST, lane);
            ldsm_x4(ah, ad);
            ldsm_x4(al, ad + (GA_AL - GA_AH));
            #pragma unroll
            for (int nt = 0; nt < 4; nt++) {
                uint32_t bd_ = lm_b_addr(sb + GA_BH, nw + nt*8, k0, GA_ST, lane);
                uint32_t bh[2], bl[2];
                ldsm_x2(bh, bd_);
                ldsm_x2(bl, bd_ + (GA_BL - GA_BH));
                mma_bf16(acc[nt], ah, bh[0], bh[1]);
                mma_bf16(acc[nt], ah, bl[0], bl[1]);
                mma_bf16(acc[nt], al, bh[0], bh[1]);
            }
        }
        __syncthreads();
    }
    #pragma unroll
    for (int nt = 0; nt < 4; nt++) {
        float* d = acc[nt];
        int c = nw + nt*8 + tig*2;
        int r = mw + gid;
        size_t base0 = ((size_t)(b*L_) + l0 + r) * 64 + c;
        size_t base1 = ((size_t)(b*L_) + l0 + r + 8) * 64 + c;
        g_sampled[base0]     = d[0];
        g_sampled[base0 + 1] = d[1];
        g_sampled[base1]     = d[2];
        g_sampled[base1 + 1] = d[3];
    }
}

// ---- K6: tokens_out via mma.sync (single K=64 chunk) ----
#define KO_ST 72
#define KO_AH 0
#define KO_AL 9216
#define KO_BH 18432
#define KO_BL 27648

__global__ void __launch_bounds__(256)
k_out(const float* __restrict__ Wf, float* __restrict__ out) {
    __shared__ __align__(16) char smem[36864];
    uint32_t sb = smem_u32(smem);
    int m0 = blockIdx.x * 64;     // token rows (b*L+l flattened)
    int e0 = blockIdx.y * 64;
    int tx = threadIdx.x;
    int lane = tx & 31, w = tx >> 5;
    int gid = lane >> 2, tig = lane & 3;
    int mw = (w & 3) * 16;
    int nw = (w >> 2) * 32;

    // stage A = sampled[m0..m0+63][0..63], B = Wf[e0..e0+63][0..63]
    #pragma unroll
    for (int j = 0; j < 8; j++) {
        int r  = w + j * 8;
        int ww = lane * 2;
        float2 g = *(const float2*)&g_sampled[(size_t)(m0 + r)*64 + ww];
        uint32_t hi, lo; split2(g.x, g.y, hi, lo);
        uint32_t off = (uint32_t)(r * KO_ST + ww) * 2;
        sts32w(sb + KO_AH + off, hi);
        sts32w(sb + KO_AL + off, lo);
        float2 g2 = *(const float2*)&Wf[(size_t)(e0 + r)*64 + ww];
        split2(g2.x, g2.y, hi, lo);
        sts32w(sb + KO_BH + off, hi);
        sts32w(sb + KO_BL + off, lo);
    }
    __syncthreads();

    float acc[4][4];
    #pragma unroll
    for (int c = 0; c < 4; c++)
        #pragma unroll
        for (int d = 0; d < 4; d++) acc[c][d] = 0.0f;
    #pragma unroll
    for (int ks = 0; ks < 4; ks++) {
        int k0 = ks * 16;
        uint32_t ah[4], al[4];
        uint32_t ad = lm_a_addr(sb + KO_AH, mw, k0, KO_ST, lane);
        ldsm_x4(ah, ad);
        ldsm_x4(al, ad + (KO_AL - KO_AH));
        #pragma unroll
        for (int nt = 0; nt < 4; nt++) {
            uint32_t bd_ = lm_b_addr(sb + KO_BH, nw + nt*8, k0, KO_ST, lane);
            uint32_t bh[2], bl[2];
            ldsm_x2(bh, bd_);
            ldsm_x2(bl, bd_ + (KO_BL - KO_BH));
            mma_bf16(acc[nt], ah, bh[0], bh[1]);
            mma_bf16(acc[nt], ah, bl[0], bl[1]);
            mma_bf16(acc[nt], al, bh[0], bh[1]);
        }
    }
    #pragma unroll
    for (int nt = 0; nt < 4; nt++) {
        float* d = acc[nt];
        int e = e0 + nw + nt*8 + tig*2;
        int r = mw + gid;
        size_t base0 = (size_t)(m0 + r) * 512 + e;
        size_t base1 = (size_t)(m0 + r + 8) * 512 + e;
        out[base0]     = d[0];
        out[base0 + 1] = d[1];
        out[base1]     = d[2];
        out[base1 + 1] = d[3];
    }
}

// ------------------------------ launch -----------------------------------
extern "C" void kernel_launch(void* const* d_in, const int* in_sizes, int n_in,
                              void* d_out, int out_size) {
    const float* tokens     = (const float*)d_in[0];
    const float* positions  = (const float*)d_in[1];
    const float* W_to_field = (const float*)d_in[2];
    const float* W_from_field = (const float*)d_in[3];
    const float* conv1_w    = (const float*)d_in[4];
    const float* conv1_b    = (const float*)d_in[5];
    const float* conv2_w    = (const float*)d_in[6];
    const float* conv2_b    = (const float*)d_in[7];
    const float* log_sigma  = (const float*)d_in[8];
    float* out = (float*)d_out;

    cudaFuncSetAttribute(k_step, cudaFuncAttributeMaxDynamicSharedMemorySize,
                         STEP_SMEM);
    cudaFuncSetAttribute(k_scatter, cudaFuncAttributeMaxDynamicSharedMemorySize,
                         SC_SMEM);
    cudaFuncSetAttribute(k_gather, cudaFuncAttributeMaxDynamicSharedMemorySize,
                         GA_SMEM);

    k_split_w<<<288, 256>>>(conv1_w, conv2_w);
    k_gauss<<<B_*L_, 64>>>(positions, log_sigma);
    k_proj<<<(B_*L_)/128, 256>>>(tokens, W_to_field);
    k_scatter<<<dim3(32, B_), 256, SC_SMEM>>>();
    for (int s = 0; s < STEPS_; s++) {
        k_step<<<dim3(32, B_), 256, STEP_SMEM>>>(conv1_b, conv2_b, s & 1);
    }
    k_gather<<<dim3(32, B_), 256, GA_SMEM>>>();
    k_out<<<dim3((B_*L_)/64, 8), 256>>>(W_from_field, out);
}

// round 16
// speedup vs baseline: 1.4002x; 1.0947x over previous
#include <cuda_runtime.h>
#include <cuda_bf16.h>
#include <math.h>
#include <stdint.h>

#define B_ 8
#define L_ 2048
#define E_ 512
#define D_ 64
#define HW 4096
#define STEPS_ 5

typedef unsigned long long u64;

// ---------------- smem / mma helpers ----------------
__device__ __forceinline__ uint32_t smem_u32(const void* p) {
    uint32_t a;
    asm("{ .reg .u64 t; cvta.to.shared.u64 t, %1; cvt.u32.u64 %0, t; }"
        : "=r"(a) : "l"(p));
    return a;
}
__device__ __forceinline__ void sts32w(uint32_t a, uint32_t v) {
    asm volatile("st.shared.b32 [%0], %1;" :: "r"(a), "r"(v));
}
__device__ __forceinline__ void ldsm_x4(uint32_t* r, uint32_t addr) {
    asm volatile("ldmatrix.sync.aligned.m8n8.x4.shared.b16 {%0,%1,%2,%3}, [%4];"
        : "=r"(r[0]), "=r"(r[1]), "=r"(r[2]), "=r"(r[3]) : "r"(addr));
}
__device__ __forceinline__ void ldsm_x2(uint32_t* r, uint32_t addr) {
    asm volatile("ldmatrix.sync.aligned.m8n8.x2.shared.b16 {%0,%1}, [%2];"
        : "=r"(r[0]), "=r"(r[1]) : "r"(addr));
}
__device__ __forceinline__ uint32_t lm_a_addr(uint32_t sbase, int mrow, int k0,
                                              int ST, int lane) {
    return sbase + (uint32_t)((mrow + (lane & 15)) * ST + k0 + ((lane >> 4) << 3)) * 2;
}
__device__ __forceinline__ uint32_t lm_b_addr(uint32_t sbase, int nrow, int k0,
                                              int ST, int lane) {
    return sbase + (uint32_t)((nrow + (lane & 7)) * ST + k0 + (((lane >> 3) & 1) << 3)) * 2;
}
__device__ __forceinline__ void mma_bf16(float* d, const uint32_t* a,
                                         uint32_t b0, uint32_t b1) {
    asm volatile(
        "mma.sync.aligned.m16n8k16.row.col.f32.bf16.bf16.f32 "
        "{%0,%1,%2,%3}, {%4,%5,%6,%7}, {%8,%9}, {%0,%1,%2,%3};"
        : "+f"(d[0]), "+f"(d[1]), "+f"(d[2]), "+f"(d[3])
        : "r"(a[0]), "r"(a[1]), "r"(a[2]), "r"(a[3]), "r"(b0), "r"(b1));
}
__device__ __forceinline__ void split2(float a0, float a1, uint32_t& hi, uint32_t& lo) {
    __nv_bfloat162 h = __floats2bfloat162_rn(a0, a1);
    float r0 = a0 - __bfloat162float(h.x);
    float r1 = a1 - __bfloat162float(h.y);
    __nv_bfloat162 l = __floats2bfloat162_rn(r0, r1);
    hi = *reinterpret_cast<uint32_t*>(&h);
    lo = *reinterpret_cast<uint32_t*>(&l);
}

// ---------------- scratch (device globals) ----------------
__device__ float g_gyi[B_*L_*64];
__device__ float g_gyiT[B_*64*L_];   // transposed: [(b*64+h)][l]
__device__ float g_gxi[B_*L_*64];
__device__ float g_gyo[B_*L_*64];
__device__ float g_gxo[B_*L_*64];
__device__ float g_proj[B_*L_*D_];
__device__ float g_field[B_*D_*HW];
__device__ float g_field2[B_*D_*HW];
__device__ float g_sampled[B_*L_*D_];
__device__ __align__(16) __nv_bfloat16 g_w1h[128*576];
__device__ __align__(16) __nv_bfloat16 g_w1l[128*576];
__device__ __align__(16) __nv_bfloat16 g_w2h[64*128];
__device__ __align__(16) __nv_bfloat16 g_w2l[64*128];

// ---------------- K-1: pre-split weights to bf16 hi/lo ----------------
__global__ void k_split_w(const float* __restrict__ w1, const float* __restrict__ w2) {
    int i = blockIdx.x * 256 + threadIdx.x;
    if (i < 128*576) {
        float v = w1[i];
        __nv_bfloat16 h = __float2bfloat16(v);
        g_w1h[i] = h;
        g_w1l[i] = __float2bfloat16(v - __bfloat162float(h));
    }
    if (i < 64*128) {
        float v = w2[i];
        __nv_bfloat16 h = __float2bfloat16(v);
        g_w2h[i] = h;
        g_w2l[i] = __float2bfloat16(v - __bfloat162float(h));
    }
}

// ---------------- K0: separable gaussians ----------------
__global__ void k_gauss(const float* __restrict__ pos,
                        const float* __restrict__ log_sigma) {
    int bl = blockIdx.x;
    int t  = threadIdx.x;
    float ls = *log_sigma;
    float si = log1pf(expf(ls)) + 1e-6f;
    float so = 2.0f * si;
    float i2si = 1.0f / (2.0f * si * si);
    float i2so = 1.0f / (2.0f * so * so);
    float py = pos[bl*2+0], px = pos[bl*2+1];
    float d  = (float)t;
    float dy2 = (d - py) * (d - py);
    float dx2 = (d - px) * (d - px);
    float gy  = expf(-dy2 * i2si);
    float gx  = expf(-dx2 * i2si);
    float gyo = expf(-dy2 * i2so);
    float gxo = expf(-dx2 * i2so);
    __shared__ float red[4][64];
    __shared__ float sums[4];
    red[0][t]=gy; red[1][t]=gx; red[2][t]=gyo; red[3][t]=gxo;
    __syncthreads();
    if (t < 4) {
        float s = 0.0f;
        #pragma unroll
        for (int i = 0; i < 64; i++) s += red[t][i];
        sums[t] = s;
    }
    __syncthreads();
    float inv_ni = 1.0f / (sums[0]*sums[1] + 1e-6f);
    float inv_no = 1.0f / (sums[2]*sums[3] + 1e-6f);
    int base = bl*64 + t;
    float gyn = gy * inv_ni;
    g_gyi[base] = gyn;
    g_gxi[base] = gx;
    g_gyo[base] = gyo * inv_no;
    g_gxo[base] = gxo;
    int b = bl >> 11, l = bl & 2047;
    g_gyiT[((size_t)(b*64) + t)*L_ + l] = gyn;
}

// ---------------- K1: proj via mma.sync (K=512, 8 chunks of 64) ----------
#define KP_ST 72
#define KP_AH 0
#define KP_AL 9216
#define KP_BH 18432
#define KP_BL 27648

__global__ void __launch_bounds__(256)
k_proj(const float* __restrict__ tokens, const float* __restrict__ Wt) {
    __shared__ __align__(16) char smem[36864];
    uint32_t sb = smem_u32(smem);
    int m0 = blockIdx.x * 64;      // token rows (b*L+l flattened)
    int tx = threadIdx.x;
    int lane = tx & 31, w = tx >> 5;
    int gid = lane >> 2, tig = lane & 3;
    int mw = (w & 3) * 16;
    int nw = (w >> 2) * 32;
    float acc[4][4];
    #pragma unroll
    for (int c = 0; c < 4; c++)
        #pragma unroll
        for (int d = 0; d < 4; d++) acc[c][d] = 0.0f;

    for (int ec = 0; ec < 8; ec++) {
        int e0 = ec * 64;
        #pragma unroll
        for (int j = 0; j < 8; j++) {
            int r  = w + j * 8;
            int ww = lane * 2;
            float2 g = *(const float2*)&tokens[(size_t)(m0 + r)*512 + e0 + ww];
            uint32_t hi, lo; split2(g.x, g.y, hi, lo);
            uint32_t off = (uint32_t)(r * KP_ST + ww) * 2;
            sts32w(sb + KP_AH + off, hi);
            sts32w(sb + KP_AL + off, lo);
            float2 g2 = *(const float2*)&Wt[(size_t)r*512 + e0 + ww];
            split2(g2.x, g2.y, hi, lo);
            sts32w(sb + KP_BH + off, hi);
            sts32w(sb + KP_BL + off, lo);
        }
        __syncthreads();
        #pragma unroll
        for (int ks = 0; ks < 4; ks++) {
            int k0 = ks * 16;
            uint32_t ah[4], al[4];
            uint32_t ad = lm_a_addr(sb + KP_AH, mw, k0, KP_ST, lane);
            ldsm_x4(ah, ad);
            ldsm_x4(al, ad + (KP_AL - KP_AH));
            #pragma unroll
            for (int nt = 0; nt < 4; nt++) {
                uint32_t bd_ = lm_b_addr(sb + KP_BH, nw + nt*8, k0, KP_ST, lane);
                uint32_t bh[2], bl[2];
                ldsm_x2(bh, bd_);
                ldsm_x2(bl, bd_ + (KP_BL - KP_BH));
                mma_bf16(acc[nt], ah, bh[0], bh[1]);
                mma_bf16(acc[nt], ah, bl[0], bl[1]);
                mma_bf16(acc[nt], al, bh[0], bh[1]);
            }
        }
        __syncthreads();
    }
    #pragma unroll
    for (int nt = 0; nt < 4; nt++) {
        float* d = acc[nt];
        int c = nw + nt*8 + tig*2;
        int r = mw + gid;
        size_t base0 = (size_t)(m0 + r) * 64 + c;
        size_t base1 = (size_t)(m0 + r + 8) * 64 + c;
        g_proj[base0]     = d[0];
        g_proj[base0 + 1] = d[1];
        g_proj[base1]     = d[2];
        g_proj[base1 + 1] = d[3];
    }
}

// ------- K2: scatter (R14-proven: K-chunk=32, static smem) -------
#define SC_ST 40
#define SC_AH 0
#define SC_AL 10240
#define SC_BH 20480
#define SC_BL 25600
#define SC_GX 30720
#define SC_GY (30720 + 32*65*4)
#define SC_SMEM (SC_GY + 64*4)

__global__ void __launch_bounds__(256) k_scatter() {
    __shared__ __align__(16) char smem[SC_SMEM];
    uint32_t sb = smem_u32(smem);
    int b  = blockIdx.y;
    int n0 = blockIdx.x * 128;
    int h0 = blockIdx.x * 2;
    int tx = threadIdx.x;
    int lane = tx & 31, w = tx >> 5;
    int gid = lane >> 2, tig = lane & 3;
    int mw = (w & 3) * 32;
    int nw = (w >> 2) * 32;
    float acc[2][4][4];
    #pragma unroll
    for (int a = 0; a < 2; a++)
        #pragma unroll
        for (int c = 0; c < 4; c++)
            #pragma unroll
            for (int d = 0; d < 4; d++) acc[a][c][d] = 0.0f;

    float* gxs = reinterpret_cast<float*>(smem + SC_GX);   // [32][65]
    float* gys = reinterpret_cast<float*>(smem + SC_GY);   // [32][2]

    for (int ch = 0; ch < 64; ch++) {
        int l0 = ch * 32;
        #pragma unroll
        for (int j = 0; j < 8; j++) {
            int i = tx + j * 256;
            int l = i >> 6, ww = i & 63;
            gxs[l*65 + ww] = g_gxi[((size_t)(b*L_) + l0 + l)*64 + ww];
        }
        if (tx < 64) {
            int h = tx >> 5, l = tx & 31;
            gys[l*2 + h] = g_gyiT[((size_t)(b*64) + h0 + h)*L_ + l0 + l];
        }
        #pragma unroll
        for (int j = 0; j < 4; j++) {
            int i = tx + j * 256;
            int c = i & 63, kc = (i >> 6) * 2;
            float b0 = g_proj[((size_t)(b*L_) + l0 + kc)*64 + c];
            float b1 = g_proj[((size_t)(b*L_) + l0 + kc + 1)*64 + c];
            uint32_t hi, lo; split2(b0, b1, hi, lo);
            uint32_t off = (uint32_t)(c * SC_ST + kc) * 2;
            sts32w(sb + SC_BH + off, hi);
            sts32w(sb + SC_BL + off, lo);
        }
        __syncthreads();
        {
            int lp = (tx & 15) * 2;
            int pg = tx >> 4;
            const float* gx0r = gxs + lp * 65;
            const float* gx1r = gx0r + 65;
            float gy0a = gys[lp*2+0],     gy0b = gys[lp*2+1];
            float gy1a = gys[(lp+1)*2+0], gy1b = gys[(lp+1)*2+1];
            #pragma unroll
            for (int i = 0; i < 8; i++) {
                int px = pg * 8 + i;
                int ww = px & 63;
                float v0 = ((px < 64) ? gy0a : gy0b) * gx0r[ww];
                float v1 = ((px < 64) ? gy1a : gy1b) * gx1r[ww];
                uint32_t hi, lo; split2(v0, v1, hi, lo);
                uint32_t off = (uint32_t)(px * SC_ST + lp) * 2;
                sts32w(sb + SC_AH + off, hi);
                sts32w(sb + SC_AL + off, lo);
            }
        }
        __syncthreads();
        #pragma unroll
        for (int ks = 0; ks < 2; ks++) {
            int k0 = ks * 16;
            uint32_t ah[2][4], al[2][4];
            #pragma unroll
            for (int mt = 0; mt < 2; mt++) {
                uint32_t ad = lm_a_addr(sb + SC_AH, mw + mt*16, k0, SC_ST, lane);
                ldsm_x4(ah[mt], ad);
                ldsm_x4(al[mt], ad + (SC_AL - SC_AH));
            }
            #pragma unroll
            for (int nt = 0; nt < 4; nt++) {
                uint32_t bd_ = lm_b_addr(sb + SC_BH, nw + nt*8, k0, SC_ST, lane);
                uint32_t bh[2], bl[2];
                ldsm_x2(bh, bd_);
                ldsm_x2(bl, bd_ + (SC_BL - SC_BH));
                #pragma unroll
                for (int mt = 0; mt < 2; mt++) {
                    mma_bf16(acc[mt][nt], ah[mt], bh[0], bh[1]);
                    mma_bf16(acc[mt][nt], ah[mt], bl[0], bl[1]);
                    mma_bf16(acc[mt][nt], al[mt], bh[0], bh[1]);
                }
            }
        }
        __syncthreads();
    }
    #pragma unroll
    for (int mt = 0; mt < 2; mt++)
        #pragma unroll
        for (int nt = 0; nt < 4; nt++) {
            float* d = acc[mt][nt];
            int c  = nw + nt*8 + tig*2;
            int r1 = mw + mt*16 + gid;
            size_t base0 = ((size_t)(b*64) + c) * HW + n0;
            size_t base1 = base0 + HW;
            g_field[base0 + r1]     = d[0];
            g_field[base1 + r1]     = d[1];
            g_field[base0 + r1 + 8] = d[2];
            g_field[base1 + r1 + 8] = d[3];
        }
}

// ---- K3: fused conv step (R14: packed im2col stores) ----
#define P1_ST 40
#define H_ST 136
#define SM_IH 0
#define SM_IL 10240
#define SM_WH 20480
#define SM_WL 30720
#define SM_W2H 0
#define SM_W2L 17408
#define SM_HH 40960
#define SM_HL 75776
#define STEP_SMEM 110592

__global__ void __launch_bounds__(256, 2)
k_step(const float* __restrict__ bias1, const float* __restrict__ bias2,
       int parity) {
    extern __shared__ __align__(16) char smem[];
    uint32_t sb = smem_u32(smem);
    const float* fin  = parity ? g_field2 : g_field;
    float*       fout = parity ? g_field  : g_field2;
    int b  = blockIdx.y;
    int y0 = blockIdx.x * 2;
    int p0 = y0 * 64;
    int tx = threadIdx.x;
    int lane = tx & 31, w = tx >> 5;
    int gid = lane >> 2, tig = lane & 3;

    int mw = (w & 3) * 32;
    int nw = (w >> 2) * 64;
    float acc[2][8][4];
    #pragma unroll
    for (int a = 0; a < 2; a++)
        #pragma unroll
        for (int c = 0; c < 8; c++)
            #pragma unroll
            for (int d = 0; d < 4; d++) acc[a][c][d] = 0.0f;

    for (int it = 0; it < 18; it++) {
        int kc0 = it * 32;
        #pragma unroll
        for (int j = 0; j < 8; j++) {
            int i = tx + j * 256;
            int px = i & 127;
            int kp = (i >> 7) * 2;
            float v0, v1;
            {
                int kap = kc0 + kp;
                int ici = kap / 9, tap = kap - ici * 9;
                int ky = tap / 3, kx = tap - ky * 3;
                int y = y0 + (px >> 6) + ky - 1;
                int x = (px & 63) + kx - 1;
                v0 = 0.0f;
                if ((unsigned)y < 64u && (unsigned)x < 64u)
                    v0 = fin[((size_t)(b*64) + ici) * HW + y * 64 + x];
            }
            {
                int kap = kc0 + kp + 1;
                int ici = kap / 9, tap = kap - ici * 9;
                int ky = tap / 3, kx = tap - ky * 3;
                int y = y0 + (px >> 6) + ky - 1;
                int x = (px & 63) + kx - 1;
                v1 = 0.0f;
                if ((unsigned)y < 64u && (unsigned)x < 64u)
                    v1 = fin[((size_t)(b*64) + ici) * HW + y * 64 + x];
            }
            uint32_t hi, lo; split2(v0, v1, hi, lo);
            uint32_t off = (uint32_t)(px * P1_ST + kp) * 2;
            sts32w(sb + SM_IH + off, hi);
            sts32w(sb + SM_IL + off, lo);
        }
        #pragma unroll
        for (int j = 0; j < 8; j++) {
            int i = tx + j * 256;
            int oc = i >> 4, kp = (i & 15) * 2;
            uint32_t vh = *(const uint32_t*)&g_w1h[oc * 576 + kc0 + kp];
            uint32_t vl = *(const uint32_t*)&g_w1l[oc * 576 + kc0 + kp];
            uint32_t off = (uint32_t)(oc * P1_ST + kp) * 2;
            sts32w(sb + SM_WH + off, vh);
            sts32w(sb + SM_WL + off, vl);
        }
        __syncthreads();
        #pragma unroll
        for (int ks = 0; ks < 2; ks++) {
            int k0 = ks * 16;
            uint32_t ah[2][4], al[2][4];
            #pragma unroll
            for (int mt = 0; mt < 2; mt++) {
                uint32_t ad = lm_a_addr(sb + SM_IH, mw + mt*16, k0, P1_ST, lane);
                ldsm_x4(ah[mt], ad);
                ldsm_x4(al[mt], ad + (SM_IL - SM_IH));
            }
            #pragma unroll
            for (int nt = 0; nt < 8; nt++) {
                uint32_t bd_ = lm_b_addr(sb + SM_WH, nw + nt*8, k0, P1_ST, lane);
                uint32_t bh[2], bl[2];
                ldsm_x2(bh, bd_);
                ldsm_x2(bl, bd_ + (SM_WL - SM_WH));
                #pragma unroll
                for (int mt = 0; mt < 2; mt++) {
                    mma_bf16(acc[mt][nt], ah[mt], bh[0], bh[1]);
                    mma_bf16(acc[mt][nt], ah[mt], bl[0], bl[1]);
                    mma_bf16(acc[mt][nt], al[mt], bh[0], bh[1]);
                }
            }
        }
        __syncthreads();
    }
    #pragma unroll
    for (int mt = 0; mt < 2; mt++)
        #pragma unroll
        for (int nt = 0; nt < 8; nt++) {
            float* d = acc[mt][nt];
            int c = nw + nt*8 + tig*2;
            float b0f = bias1[c], b1f = bias1[c+1];
            int r1 = mw + mt*16 + gid;
            float h00 = fmaxf(d[0] + b0f, 0.f), h01 = fmaxf(d[1] + b1f, 0.f);
            float h10 = fmaxf(d[2] + b0f, 0.f), h11 = fmaxf(d[3] + b1f, 0.f);
            uint32_t hi0, lo0, hi1, lo1;
            split2(h00, h01, hi0, lo0);
            split2(h10, h11, hi1, lo1);
            uint32_t o1 = (uint32_t)(r1 * H_ST + c) * 2;
            uint32_t o2 = (uint32_t)((r1+8) * H_ST + c) * 2;
            sts32w(sb + SM_HH + o1, hi0); sts32w(sb + SM_HL + o1, lo0);
            sts32w(sb + SM_HH + o2, hi1); sts32w(sb + SM_HL + o2, lo1);
        }
    #pragma unroll
    for (int j = 0; j < 16; j++) {
        int i = tx + j * 256;
        int c = i >> 6, hp = (i & 63) * 2;
        uint32_t vh = *(const uint32_t*)&g_w2h[c * 128 + hp];
        uint32_t vl = *(const uint32_t*)&g_w2l[c * 128 + hp];
        uint32_t off = (uint32_t)(c * H_ST + hp) * 2;
        sts32w(sb + SM_W2H + off, vh);
        sts32w(sb + SM_W2L + off, vl);
    }
    __syncthreads();

    int mw2 = (w & 3) * 32;
    int nw2 = (w >> 2) * 32;
    float acc2[2][4][4];
    #pragma unroll
    for (int a = 0; a < 2; a++)
        #pragma unroll
        for (int c = 0; c < 4; c++)
            #pragma unroll
            for (int d = 0; d < 4; d++) acc2[a][c][d] = 0.0f;
    #pragma unroll
    for (int ks = 0; ks < 8; ks++) {
        int k0 = ks * 16;
        uint32_t ah[2][4], al[2][4];
        #pragma unroll
        for (int mt = 0; mt < 2; mt++) {
            uint32_t ad = lm_a_addr(sb + SM_HH, mw2 + mt*16, k0, H_ST, lane);
            ldsm_x4(ah[mt], ad);
            ldsm_x4(al[mt], ad + (SM_HL - SM_HH));
        }
        #pragma unroll
        for (int nt = 0; nt < 4; nt++) {
            uint32_t bd_ = lm_b_addr(sb + SM_W2H, nw2 + nt*8, k0, H_ST, lane);
            uint32_t bh[2], bl[2];
            ldsm_x2(bh, bd_);
            ldsm_x2(bl, bd_ + (SM_W2L - SM_W2H));
            #pragma unroll
            for (int mt = 0; mt < 2; mt++) {
                mma_bf16(acc2[mt][nt], ah[mt], bh[0], bh[1]);
                mma_bf16(acc2[mt][nt], ah[mt], bl[0], bl[1]);
                mma_bf16(acc2[mt][nt], al[mt], bh[0], bh[1]);
            }
        }
    }
    #pragma unroll
    for (int mt = 0; mt < 2; mt++)
        #pragma unroll
        for (int nt = 0; nt < 4; nt++) {
            float* d = acc2[mt][nt];
            int c = nw2 + nt*8 + tig*2;
            int r1 = mw2 + mt*16 + gid;
            float b0f = bias2[c], b1f = bias2[c+1];
            size_t base0 = ((size_t)(b*64) + c) * HW + p0;
            size_t base1 = base0 + HW;
            fout[base0 + r1]     = d[0] + b0f + fin[base0 + r1];
            fout[base1 + r1]     = d[1] + b1f + fin[base1 + r1];
            fout[base0 + r1 + 8] = d[2] + b0f + fin[base0 + r1 + 8];
            fout[base1 + r1 + 8] = d[3] + b1f + fin[base1 + r1 + 8];
        }
}

// ---- K5: gather, 2 h-rows per iteration (R15-proven) ----
#define GA_ST 136
#define GA_AH 0
#define GA_AL 17408
#define GA_BH 34816
#define GA_BL 52224
#define GA_SMEM 69632

__global__ void __launch_bounds__(256) k_gather() {
    extern __shared__ __align__(16) char smem[];
    uint32_t sb = smem_u32(smem);
    int b  = blockIdx.y;
    int l0 = blockIdx.x * 64;
    int tx = threadIdx.x;
    int lane = tx & 31, w = tx >> 5;
    int gid = lane >> 2, tig = lane & 3;
    int mw = (w & 3) * 16;
    int nw = (w >> 2) * 32;
    float acc[4][4];
    #pragma unroll
    for (int c = 0; c < 4; c++)
        #pragma unroll
        for (int d = 0; d < 4; d++) acc[c][d] = 0.0f;

    for (int h2 = 0; h2 < 32; h2++) {
        int h = h2 * 2;
        #pragma unroll
        for (int j = 0; j < 8; j++) {
            int r  = w + j * 8;
            int ww = lane * 2;
            int lg = b * L_ + l0 + r;
            float2 g = *(const float2*)&g_gxo[(size_t)lg*64 + ww];
            float gy0 = g_gyo[(size_t)lg*64 + h];
            float gy1 = g_gyo[(size_t)lg*64 + h + 1];
            uint32_t hi, lo;
            split2(gy0 * g.x, gy0 * g.y, hi, lo);
            uint32_t off = (uint32_t)(r * GA_ST + ww) * 2;
            sts32w(sb + GA_AH + off, hi);
            sts32w(sb + GA_AL + off, lo);
            split2(gy1 * g.x, gy1 * g.y, hi, lo);
            off = (uint32_t)(r * GA_ST + 64 + ww) * 2;
            sts32w(sb + GA_AH + off, hi);
            sts32w(sb + GA_AL + off, lo);
        }
        #pragma unroll
        for (int j = 0; j < 8; j++) {
            int r  = w + j * 8;
            int ww = lane * 2;
            const float* fr = &g_field2[((size_t)(b*64) + r)*HW + h*64];
            float2 g0 = *(const float2*)&fr[ww];
            float2 g1 = *(const float2*)&fr[64 + ww];
            uint32_t hi, lo;
            split2(g0.x, g0.y, hi, lo);
            uint32_t off = (uint32_t)(r * GA_ST + ww) * 2;
            sts32w(sb + GA_BH + off, hi);
            sts32w(sb + GA_BL + off, lo);
            split2(g1.x, g1.y, hi, lo);
            off = (uint32_t)(r * GA_ST + 64 + ww) * 2;
            sts32w(sb + GA_BH + off, hi);
            sts32w(sb + GA_BL + off, lo);
        }
        __syncthreads();
        #pragma unroll
        for (int ks = 0; ks < 8; ks++) {
            int k0 = ks * 16;
            uint32_t ah[4], al[4];
            uint32_t ad = lm_a_addr(sb + GA_AH, mw, k0, GA_ST, lane);
            ldsm_x4(ah, ad);
            ldsm_x4(al, ad + (GA_AL - GA_AH));
            #pragma unroll
            for (int nt = 0; nt < 4; nt++) {
                uint32_t bd_ = lm_b_addr(sb + GA_BH, nw + nt*8, k0, GA_ST, lane);
                uint32_t bh[2], bl[2];
                ldsm_x2(bh, bd_);
                ldsm_x2(bl, bd_ + (GA_BL - GA_BH));
                mma_bf16(acc[nt], ah, bh[0], bh[1]);
                mma_bf16(acc[nt], ah, bl[0], bl[1]);
                mma_bf16(acc[nt], al, bh[0], bh[1]);
            }
        }
        __syncthreads();
    }
    #pragma unroll
    for (int nt = 0; nt < 4; nt++) {
        float* d = acc[nt];
        int c = nw + nt*8 + tig*2;
        int r = mw + gid;
        size_t base0 = ((size_t)(b*L_) + l0 + r) * 64 + c;
        size_t base1 = ((size_t)(b*L_) + l0 + r + 8) * 64 + c;
        g_sampled[base0]     = d[0];
        g_sampled[base0 + 1] = d[1];
        g_sampled[base1]     = d[2];
        g_sampled[base1 + 1] = d[3];
    }
}

// ---- K6: tokens_out via mma.sync (R15-proven) ----
#define KO_ST 72
#define KO_AH 0
#define KO_AL 9216
#define KO_BH 18432
#define KO_BL 27648

__global__ void __launch_bounds__(256)
k_out(const float* __restrict__ Wf, float* __restrict__ out) {
    __shared__ __align__(16) char smem[36864];
    uint32_t sb = smem_u32(smem);
    int m0 = blockIdx.x * 64;
    int e0 = blockIdx.y * 64;
    int tx = threadIdx.x;
    int lane = tx & 31, w = tx >> 5;
    int gid = lane >> 2, tig = lane & 3;
    int mw = (w & 3) * 16;
    int nw = (w >> 2) * 32;

    #pragma unroll
    for (int j = 0; j < 8; j++) {
        int r  = w + j * 8;
        int ww = lane * 2;
        float2 g = *(const float2*)&g_sampled[(size_t)(m0 + r)*64 + ww];
        uint32_t hi, lo; split2(g.x, g.y, hi, lo);
        uint32_t off = (uint32_t)(r * KO_ST + ww) * 2;
        sts32w(sb + KO_AH + off, hi);
        sts32w(sb + KO_AL + off, lo);
        float2 g2 = *(const float2*)&Wf[(size_t)(e0 + r)*64 + ww];
        split2(g2.x, g2.y, hi, lo);
        sts32w(sb + KO_BH + off, hi);
        sts32w(sb + KO_BL + off, lo);
    }
    __syncthreads();

    float acc[4][4];
    #pragma unroll
    for (int c = 0; c < 4; c++)
        #pragma unroll
        for (int d = 0; d < 4; d++) acc[c][d] = 0.0f;
    #pragma unroll
    for (int ks = 0; ks < 4; ks++) {
        int k0 = ks * 16;
        uint32_t ah[4], al[4];
        uint32_t ad = lm_a_addr(sb + KO_AH, mw, k0, KO_ST, lane);
        ldsm_x4(ah, ad);
        ldsm_x4(al, ad + (KO_AL - KO_AH));
        #pragma unroll
        for (int nt = 0; nt < 4; nt++) {
            uint32_t bd_ = lm_b_addr(sb + KO_BH, nw + nt*8, k0, KO_ST, lane);
            uint32_t bh[2], bl[2];
            ldsm_x2(bh, bd_);
            ldsm_x2(bl, bd_ + (KO_BL - KO_BH));
            mma_bf16(acc[nt], ah, bh[0], bh[1]);
            mma_bf16(acc[nt], ah, bl[0], bl[1]);
            mma_bf16(acc[nt], al, bh[0], bh[1]);
        }
    }
    #pragma unroll
    for (int nt = 0; nt < 4; nt++) {
        float* d = acc[nt];
        int e = e0 + nw + nt*8 + tig*2;
        int r = mw + gid;
        size_t base0 = (size_t)(m0 + r) * 512 + e;
        size_t base1 = (size_t)(m0 + r + 8) * 512 + e;
        out[base0]     = d[0];
        out[base0 + 1] = d[1];
        out[base1]     = d[2];
        out[base1 + 1] = d[3];
    }
}

// ------------------------------ launch -----------------------------------
extern "C" void kernel_launch(void* const* d_in, const int* in_sizes, int n_in,
                              void* d_out, int out_size) {
    const float* tokens     = (const float*)d_in[0];
    const float* positions  = (const float*)d_in[1];
    const float* W_to_field = (const float*)d_in[2];
    const float* W_from_field = (const float*)d_in[3];
    const float* conv1_w    = (const float*)d_in[4];
    const float* conv1_b    = (const float*)d_in[5];
    const float* conv2_w    = (const float*)d_in[6];
    const float* conv2_b    = (const float*)d_in[7];
    const float* log_sigma  = (const float*)d_in[8];
    float* out = (float*)d_out;

    cudaFuncSetAttribute(k_step, cudaFuncAttributeMaxDynamicSharedMemorySize,
                         STEP_SMEM);
    cudaFuncSetAttribute(k_gather, cudaFuncAttributeMaxDynamicSharedMemorySize,
                         GA_SMEM);

    k_split_w<<<288, 256>>>(conv1_w, conv2_w);
    k_gauss<<<B_*L_, 64>>>(positions, log_sigma);
    k_proj<<<(B_*L_)/64, 256>>>(tokens, W_to_field);
    k_scatter<<<dim3(32, B_), 256>>>();
    for (int s = 0; s < STEPS_; s++) {
        k_step<<<dim3(32, B_), 256, STEP_SMEM>>>(conv1_b, conv2_b, s & 1);
    }
    k_gather<<<dim3(32, B_), 256, GA_SMEM>>>();
    k_out<<<dim3((B_*L_)/64, 8), 256>>>(W_from_field, out);
}

// round 17
// speedup vs baseline: 1.5281x; 1.0913x over previous
#include <cuda_runtime.h>
#include <cuda_bf16.h>
#include <math.h>
#include <stdint.h>

#define B_ 8
#define L_ 2048
#define E_ 512
#define D_ 64
#define HW 4096
#define STEPS_ 5

typedef unsigned long long u64;

// ---------------- smem / mma helpers ----------------
__device__ __forceinline__ uint32_t smem_u32(const void* p) {
    uint32_t a;
    asm("{ .reg .u64 t; cvta.to.shared.u64 t, %1; cvt.u32.u64 %0, t; }"
        : "=r"(a) : "l"(p));
    return a;
}
__device__ __forceinline__ void sts32w(uint32_t a, uint32_t v) {
    asm volatile("st.shared.b32 [%0], %1;" :: "r"(a), "r"(v));
}
#define CP_ASYNC16(dst, src) \
    asm volatile("cp.async.cg.shared.global [%0], [%1], 16;" :: "r"(dst), "l"(src))
#define CP_ASYNC4(dst, src) \
    asm volatile("cp.async.ca.shared.global [%0], [%1], 4;" :: "r"(dst), "l"(src))
#define CP_COMMIT() asm volatile("cp.async.commit_group;" ::: "memory")
#define CP_WAIT0()  asm volatile("cp.async.wait_group 0;" ::: "memory")

__device__ __forceinline__ void ldsm_x4(uint32_t* r, uint32_t addr) {
    asm volatile("ldmatrix.sync.aligned.m8n8.x4.shared.b16 {%0,%1,%2,%3}, [%4];"
        : "=r"(r[0]), "=r"(r[1]), "=r"(r[2]), "=r"(r[3]) : "r"(addr));
}
__device__ __forceinline__ uint32_t lm_a_addr(uint32_t sbase, int mrow, int k0,
                                              int ST, int lane) {
    return sbase + (uint32_t)((mrow + (lane & 15)) * ST + k0 + ((lane >> 4) << 3)) * 2;
}
// B x4: loads two adjacent 8-row n-tiles (16 rows x 16 k)
// lanes 0-7: rows n0-7 k0 | 8-15: n0-7 k8 | 16-23: n8-15 k0 | 24-31: n8-15 k8
// -> r0,r1 = (b0,b1) tile nt ; r2,r3 = (b0,b1) tile nt+1
__device__ __forceinline__ uint32_t lm_b4_addr(uint32_t sbase, int nrow, int k0,
                                               int ST, int lane) {
    return sbase + (uint32_t)((nrow + (lane & 7) + ((lane >> 4) << 3)) * ST
                              + k0 + (((lane >> 3) & 1) << 3)) * 2;
}
__device__ __forceinline__ void mma_bf16(float* d, const uint32_t* a,
                                         uint32_t b0, uint32_t b1) {
    asm volatile(
        "mma.sync.aligned.m16n8k16.row.col.f32.bf16.bf16.f32 "
        "{%0,%1,%2,%3}, {%4,%5,%6,%7}, {%8,%9}, {%0,%1,%2,%3};"
        : "+f"(d[0]), "+f"(d[1]), "+f"(d[2]), "+f"(d[3])
        : "r"(a[0]), "r"(a[1]), "r"(a[2]), "r"(a[3]), "r"(b0), "r"(b1));
}
__device__ __forceinline__ void split2(float a0, float a1, uint32_t& hi, uint32_t& lo) {
    __nv_bfloat162 h = __floats2bfloat162_rn(a0, a1);
    float r0 = a0 - __bfloat162float(h.x);
    float r1 = a1 - __bfloat162float(h.y);
    __nv_bfloat162 l = __floats2bfloat162_rn(r0, r1);
    hi = *reinterpret_cast<uint32_t*>(&h);
    lo = *reinterpret_cast<uint32_t*>(&l);
}

// ---------------- scratch (device globals) ----------------
__device__ float g_gyi[B_*L_*64];
__device__ float g_gyiT[B_*64*L_];
__device__ float g_gxi[B_*L_*64];
__device__ float g_gyo[B_*L_*64];
__device__ float g_gxo[B_*L_*64];
__device__ float g_proj[B_*L_*D_];
__device__ float g_field[B_*D_*HW];
__device__ float g_field2[B_*D_*HW];
__device__ float g_sampled[B_*L_*D_];
__device__ __align__(16) __nv_bfloat16 g_w1h[128*576];
__device__ __align__(16) __nv_bfloat16 g_w1l[128*576];
__device__ __align__(16) __nv_bfloat16 g_w2h[64*128];
__device__ __align__(16) __nv_bfloat16 g_w2l[64*128];

// ---------------- K-1: pre-split weights to bf16 hi/lo ----------------
__global__ void k_split_w(const float* __restrict__ w1, const float* __restrict__ w2) {
    int i = blockIdx.x * 256 + threadIdx.x;
    if (i < 128*576) {
        float v = w1[i];
        __nv_bfloat16 h = __float2bfloat16(v);
        g_w1h[i] = h;
        g_w1l[i] = __float2bfloat16(v - __bfloat162float(h));
    }
    if (i < 64*128) {
        float v = w2[i];
        __nv_bfloat16 h = __float2bfloat16(v);
        g_w2h[i] = h;
        g_w2l[i] = __float2bfloat16(v - __bfloat162float(h));
    }
}

// ---------------- K0: separable gaussians ----------------
__global__ void k_gauss(const float* __restrict__ pos,
                        const float* __restrict__ log_sigma) {
    int bl = blockIdx.x;
    int t  = threadIdx.x;
    float ls = *log_sigma;
    float si = log1pf(expf(ls)) + 1e-6f;
    float so = 2.0f * si;
    float i2si = 1.0f / (2.0f * si * si);
    float i2so = 1.0f / (2.0f * so * so);
    float py = pos[bl*2+0], px = pos[bl*2+1];
    float d  = (float)t;
    float dy2 = (d - py) * (d - py);
    float dx2 = (d - px) * (d - px);
    float gy  = expf(-dy2 * i2si);
    float gx  = expf(-dx2 * i2si);
    float gyo = expf(-dy2 * i2so);
    float gxo = expf(-dx2 * i2so);
    __shared__ float red[4][64];
    __shared__ float sums[4];
    red[0][t]=gy; red[1][t]=gx; red[2][t]=gyo; red[3][t]=gxo;
    __syncthreads();
    if (t < 4) {
        float s = 0.0f;
        #pragma unroll
        for (int i = 0; i < 64; i++) s += red[t][i];
        sums[t] = s;
    }
    __syncthreads();
    float inv_ni = 1.0f / (sums[0]*sums[1] + 1e-6f);
    float inv_no = 1.0f / (sums[2]*sums[3] + 1e-6f);
    int base = bl*64 + t;
    float gyn = gy * inv_ni;
    g_gyi[base] = gyn;
    g_gxi[base] = gx;
    g_gyo[base] = gyo * inv_no;
    g_gxo[base] = gxo;
    int b = bl >> 11, l = bl & 2047;
    g_gyiT[((size_t)(b*64) + t)*L_ + l] = gyn;
}

// ---------------- K1: proj via mma.sync ----------
#define KP_ST 72
#define KP_AH 0
#define KP_AL 9216
#define KP_BH 18432
#define KP_BL 27648

__global__ void __launch_bounds__(256)
k_proj(const float* __restrict__ tokens, const float* __restrict__ Wt) {
    __shared__ __align__(16) char smem[36864];
    uint32_t sb = smem_u32(smem);
    int m0 = blockIdx.x * 64;
    int tx = threadIdx.x;
    int lane = tx & 31, w = tx >> 5;
    int gid = lane >> 2, tig = lane & 3;
    int mw = (w & 3) * 16;
    int nw = (w >> 2) * 32;
    float acc[4][4];
    #pragma unroll
    for (int c = 0; c < 4; c++)
        #pragma unroll
        for (int d = 0; d < 4; d++) acc[c][d] = 0.0f;

    for (int ec = 0; ec < 8; ec++) {
        int e0 = ec * 64;
        #pragma unroll
        for (int j = 0; j < 8; j++) {
            int r  = w + j * 8;
            int ww = lane * 2;
            float2 g = *(const float2*)&tokens[(size_t)(m0 + r)*512 + e0 + ww];
            uint32_t hi, lo; split2(g.x, g.y, hi, lo);
            uint32_t off = (uint32_t)(r * KP_ST + ww) * 2;
            sts32w(sb + KP_AH + off, hi);
            sts32w(sb + KP_AL + off, lo);
            float2 g2 = *(const float2*)&Wt[(size_t)r*512 + e0 + ww];
            split2(g2.x, g2.y, hi, lo);
            sts32w(sb + KP_BH + off, hi);
            sts32w(sb + KP_BL + off, lo);
        }
        __syncthreads();
        #pragma unroll
        for (int ks = 0; ks < 4; ks++) {
            int k0 = ks * 16;
            uint32_t ah[4], al[4];
            uint32_t ad = lm_a_addr(sb + KP_AH, mw, k0, KP_ST, lane);
            ldsm_x4(ah, ad);
            ldsm_x4(al, ad + (KP_AL - KP_AH));
            #pragma unroll
            for (int p = 0; p < 2; p++) {
                uint32_t bd_ = lm_b4_addr(sb + KP_BH, nw + p*16, k0, KP_ST, lane);
                uint32_t bh[4], bl[4];
                ldsm_x4(bh, bd_);
                ldsm_x4(bl, bd_ + (KP_BL - KP_BH));
                mma_bf16(acc[2*p],   ah, bh[0], bh[1]);
                mma_bf16(acc[2*p],   ah, bl[0], bl[1]);
                mma_bf16(acc[2*p],   al, bh[0], bh[1]);
                mma_bf16(acc[2*p+1], ah, bh[2], bh[3]);
                mma_bf16(acc[2*p+1], ah, bl[2], bl[3]);
                mma_bf16(acc[2*p+1], al, bh[2], bh[3]);
            }
        }
        __syncthreads();
    }
    #pragma unroll
    for (int nt = 0; nt < 4; nt++) {
        float* d = acc[nt];
        int c = nw + nt*8 + tig*2;
        int r = mw + gid;
        size_t base0 = (size_t)(m0 + r) * 64 + c;
        size_t base1 = (size_t)(m0 + r + 8) * 64 + c;
        g_proj[base0]     = d[0];
        g_proj[base0 + 1] = d[1];
        g_proj[base1]     = d[2];
        g_proj[base1 + 1] = d[3];
    }
}

// ------- K2: scatter (K-chunk=32) -------
#define SC_ST 40
#define SC_AH 0
#define SC_AL 10240
#define SC_BH 20480
#define SC_BL 25600
#define SC_GX 30720
#define SC_GY (30720 + 32*65*4)
#define SC_SMEM (SC_GY + 64*4)

__global__ void __launch_bounds__(256) k_scatter() {
    __shared__ __align__(16) char smem[SC_SMEM];
    uint32_t sb = smem_u32(smem);
    int b  = blockIdx.y;
    int n0 = blockIdx.x * 128;
    int h0 = blockIdx.x * 2;
    int tx = threadIdx.x;
    int lane = tx & 31, w = tx >> 5;
    int gid = lane >> 2, tig = lane & 3;
    int mw = (w & 3) * 32;
    int nw = (w >> 2) * 32;
    float acc[2][4][4];
    #pragma unroll
    for (int a = 0; a < 2; a++)
        #pragma unroll
        for (int c = 0; c < 4; c++)
            #pragma unroll
            for (int d = 0; d < 4; d++) acc[a][c][d] = 0.0f;

    float* gxs = reinterpret_cast<float*>(smem + SC_GX);

    for (int ch = 0; ch < 64; ch++) {
        int l0 = ch * 32;
        // gx slab + gy pairs via cp.async (pure fp32 copies)
        #pragma unroll
        for (int j = 0; j < 8; j++) {
            int i = tx + j * 256;
            int l = i >> 6, ww = i & 63;
            uint32_t dst = sb + SC_GX + (uint32_t)(l*65 + ww) * 4;
            CP_ASYNC4(dst, &g_gxi[((size_t)(b*L_) + l0 + l)*64 + ww]);
        }
        if (tx < 64) {
            int h = tx >> 5, l = tx & 31;
            uint32_t dst = sb + SC_GY + (uint32_t)(l*2 + h) * 4;
            CP_ASYNC4(dst, &g_gyiT[((size_t)(b*64) + h0 + h)*L_ + l0 + l]);
        }
        CP_COMMIT();
        #pragma unroll
        for (int j = 0; j < 4; j++) {
            int i = tx + j * 256;
            int c = i & 63, kc = (i >> 6) * 2;
            float b0 = g_proj[((size_t)(b*L_) + l0 + kc)*64 + c];
            float b1 = g_proj[((size_t)(b*L_) + l0 + kc + 1)*64 + c];
            uint32_t hi, lo; split2(b0, b1, hi, lo);
            uint32_t off = (uint32_t)(c * SC_ST + kc) * 2;
            sts32w(sb + SC_BH + off, hi);
            sts32w(sb + SC_BL + off, lo);
        }
        CP_WAIT0();
        __syncthreads();
        {
            float* gys = reinterpret_cast<float*>(smem + SC_GY);
            int lp = (tx & 15) * 2;
            int pg = tx >> 4;
            const float* gx0r = gxs + lp * 65;
            const float* gx1r = gx0r + 65;
            float gy0a = gys[lp*2+0],     gy0b = gys[lp*2+1];
            float gy1a = gys[(lp+1)*2+0], gy1b = gys[(lp+1)*2+1];
            #pragma unroll
            for (int i = 0; i < 8; i++) {
                int px = pg * 8 + i;
                int ww = px & 63;
                float v0 = ((px < 64) ? gy0a : gy0b) * gx0r[ww];
                float v1 = ((px < 64) ? gy1a : gy1b) * gx1r[ww];
                uint32_t hi, lo; split2(v0, v1, hi, lo);
                uint32_t off = (uint32_t)(px * SC_ST + lp) * 2;
                sts32w(sb + SC_AH + off, hi);
                sts32w(sb + SC_AL + off, lo);
            }
        }
        __syncthreads();
        #pragma unroll
        for (int ks = 0; ks < 2; ks++) {
            int k0 = ks * 16;
            uint32_t ah[2][4], al[2][4];
            #pragma unroll
            for (int mt = 0; mt < 2; mt++) {
                uint32_t ad = lm_a_addr(sb + SC_AH, mw + mt*16, k0, SC_ST, lane);
                ldsm_x4(ah[mt], ad);
                ldsm_x4(al[mt], ad + (SC_AL - SC_AH));
            }
            #pragma unroll
            for (int p = 0; p < 2; p++) {
                uint32_t bd_ = lm_b4_addr(sb + SC_BH, nw + p*16, k0, SC_ST, lane);
                uint32_t bh[4], bl[4];
                ldsm_x4(bh, bd_);
                ldsm_x4(bl, bd_ + (SC_BL - SC_BH));
                #pragma unroll
                for (int mt = 0; mt < 2; mt++) {
                    mma_bf16(acc[mt][2*p],   ah[mt], bh[0], bh[1]);
                    mma_bf16(acc[mt][2*p],   ah[mt], bl[0], bl[1]);
                    mma_bf16(acc[mt][2*p],   al[mt], bh[0], bh[1]);
                    mma_bf16(acc[mt][2*p+1], ah[mt], bh[2], bh[3]);
                    mma_bf16(acc[mt][2*p+1], ah[mt], bl[2], bl[3]);
                    mma_bf16(acc[mt][2*p+1], al[mt], bh[2], bh[3]);
                }
            }
        }
        __syncthreads();
    }
    #pragma unroll
    for (int mt = 0; mt < 2; mt++)
        #pragma unroll
        for (int nt = 0; nt < 4; nt++) {
            float* d = acc[mt][nt];
            int c  = nw + nt*8 + tig*2;
            int r1 = mw + mt*16 + gid;
            size_t base0 = ((size_t)(b*64) + c) * HW + n0;
            size_t base1 = base0 + HW;
            g_field[base0 + r1]     = d[0];
            g_field[base1 + r1]     = d[1];
            g_field[base0 + r1 + 8] = d[2];
            g_field[base1 + r1 + 8] = d[3];
        }
}

// ---- K3: fused conv step ----
#define P1_ST 40
#define H_ST 136
#define SM_IH 0
#define SM_IL 10240
#define SM_WH 20480
#define SM_WL 30720
#define SM_W2H 0
#define SM_W2L 17408
#define SM_HH 40960
#define SM_HL 75776
#define STEP_SMEM 110592

__global__ void __launch_bounds__(256, 2)
k_step(const float* __restrict__ bias1, const float* __restrict__ bias2,
       int parity) {
    extern __shared__ __align__(16) char smem[];
    uint32_t sb = smem_u32(smem);
    const float* fin  = parity ? g_field2 : g_field;
    float*       fout = parity ? g_field  : g_field2;
    int b  = blockIdx.y;
    int y0 = blockIdx.x * 2;
    int p0 = y0 * 64;
    int tx = threadIdx.x;
    int lane = tx & 31, w = tx >> 5;
    int gid = lane >> 2, tig = lane & 3;

    int mw = (w & 3) * 32;
    int nw = (w >> 2) * 64;
    float acc[2][8][4];
    #pragma unroll
    for (int a = 0; a < 2; a++)
        #pragma unroll
        for (int c = 0; c < 8; c++)
            #pragma unroll
            for (int d = 0; d < 4; d++) acc[a][c][d] = 0.0f;

    for (int it = 0; it < 18; it++) {
        int kc0 = it * 32;
        // W1 staging via cp.async.16 (pure bf16 copy)
        #pragma unroll
        for (int j = 0; j < 4; j++) {
            int i = tx + j * 256;          // 0..1023
            int buf = i >> 9;
            int t = i & 511;
            int oc = t >> 2;
            int seg = (t & 3) * 8;
            const __nv_bfloat16* src =
                (buf ? g_w1l : g_w1h) + oc * 576 + kc0 + seg;
            uint32_t dst = sb + (buf ? SM_WL : SM_WH) +
                           (uint32_t)(oc * P1_ST + seg) * 2;
            CP_ASYNC16(dst, src);
        }
        CP_COMMIT();
        // im2col staging (packed pairs)
        #pragma unroll
        for (int j = 0; j < 8; j++) {
            int i = tx + j * 256;
            int px = i & 127;
            int kp = (i >> 7) * 2;
            float v0, v1;
            {
                int kap = kc0 + kp;
                int ici = kap / 9, tap = kap - ici * 9;
                int ky = tap / 3, kx = tap - ky * 3;
                int y = y0 + (px >> 6) + ky - 1;
                int x = (px & 63) + kx - 1;
                v0 = 0.0f;
                if ((unsigned)y < 64u && (unsigned)x < 64u)
                    v0 = fin[((size_t)(b*64) + ici) * HW + y * 64 + x];
            }
            {
                int kap = kc0 + kp + 1;
                int ici = kap / 9, tap = kap - ici * 9;
                int ky = tap / 3, kx = tap - ky * 3;
                int y = y0 + (px >> 6) + ky - 1;
                int x = (px & 63) + kx - 1;
                v1 = 0.0f;
                if ((unsigned)y < 64u && (unsigned)x < 64u)
                    v1 = fin[((size_t)(b*64) + ici) * HW + y * 64 + x];
            }
            uint32_t hi, lo; split2(v0, v1, hi, lo);
            uint32_t off = (uint32_t)(px * P1_ST + kp) * 2;
            sts32w(sb + SM_IH + off, hi);
            sts32w(sb + SM_IL + off, lo);
        }
        CP_WAIT0();
        __syncthreads();
        #pragma unroll
        for (int ks = 0; ks < 2; ks++) {
            int k0 = ks * 16;
            uint32_t ah[2][4], al[2][4];
            #pragma unroll
            for (int mt = 0; mt < 2; mt++) {
                uint32_t ad = lm_a_addr(sb + SM_IH, mw + mt*16, k0, P1_ST, lane);
                ldsm_x4(ah[mt], ad);
                ldsm_x4(al[mt], ad + (SM_IL - SM_IH));
            }
            #pragma unroll
            for (int p = 0; p < 4; p++) {
                uint32_t bd_ = lm_b4_addr(sb + SM_WH, nw + p*16, k0, P1_ST, lane);
                uint32_t bh[4], bl[4];
                ldsm_x4(bh, bd_);
                ldsm_x4(bl, bd_ + (SM_WL - SM_WH));
                #pragma unroll
                for (int mt = 0; mt < 2; mt++) {
                    mma_bf16(acc[mt][2*p],   ah[mt], bh[0], bh[1]);
                    mma_bf16(acc[mt][2*p],   ah[mt], bl[0], bl[1]);
                    mma_bf16(acc[mt][2*p],   al[mt], bh[0], bh[1]);
                    mma_bf16(acc[mt][2*p+1], ah[mt], bh[2], bh[3]);
                    mma_bf16(acc[mt][2*p+1], ah[mt], bl[2], bl[3]);
                    mma_bf16(acc[mt][2*p+1], al[mt], bh[2], bh[3]);
                }
            }
        }
        __syncthreads();
    }
    #pragma unroll
    for (int mt = 0; mt < 2; mt++)
        #pragma unroll
        for (int nt = 0; nt < 8; nt++) {
            float* d = acc[mt][nt];
            int c = nw + nt*8 + tig*2;
            float b0f = bias1[c], b1f = bias1[c+1];
            int r1 = mw + mt*16 + gid;
            float h00 = fmaxf(d[0] + b0f, 0.f), h01 = fmaxf(d[1] + b1f, 0.f);
            float h10 = fmaxf(d[2] + b0f, 0.f), h11 = fmaxf(d[3] + b1f, 0.f);
            uint32_t hi0, lo0, hi1, lo1;
            split2(h00, h01, hi0, lo0);
            split2(h10, h11, hi1, lo1);
            uint32_t o1 = (uint32_t)(r1 * H_ST + c) * 2;
            uint32_t o2 = (uint32_t)((r1+8) * H_ST + c) * 2;
            sts32w(sb + SM_HH + o1, hi0); sts32w(sb + SM_HL + o1, lo0);
            sts32w(sb + SM_HH + o2, hi1); sts32w(sb + SM_HL + o2, lo1);
        }
    // W2 staging via cp.async.16
    #pragma unroll
    for (int j = 0; j < 8; j++) {
        int i = tx + j * 256;              // 0..2047
        int buf = i >> 10;
        int t = i & 1023;
        int c = t >> 4;
        int seg = (t & 15) * 8;
        const __nv_bfloat16* src = (buf ? g_w2l : g_w2h) + c * 128 + seg;
        uint32_t dst = sb + (buf ? SM_W2L : SM_W2H) +
                       (uint32_t)(c * H_ST + seg) * 2;
        CP_ASYNC16(dst, src);
    }
    CP_COMMIT();
    CP_WAIT0();
    __syncthreads();

    int mw2 = (w & 3) * 32;
    int nw2 = (w >> 2) * 32;
    float acc2[2][4][4];
    #pragma unroll
    for (int a = 0; a < 2; a++)
        #pragma unroll
        for (int c = 0; c < 4; c++)
            #pragma unroll
            for (int d = 0; d < 4; d++) acc2[a][c][d] = 0.0f;
    #pragma unroll
    for (int ks = 0; ks < 8; ks++) {
        int k0 = ks * 16;
        uint32_t ah[2][4], al[2][4];
        #pragma unroll
        for (int mt = 0; mt < 2; mt++) {
            uint32_t ad = lm_a_addr(sb + SM_HH, mw2 + mt*16, k0, H_ST, lane);
            ldsm_x4(ah[mt], ad);
            ldsm_x4(al[mt], ad + (SM_HL - SM_HH));
        }
        #pragma unroll
        for (int p = 0; p < 2; p++) {
            uint32_t bd_ = lm_b4_addr(sb + SM_W2H, nw2 + p*16, k0, H_ST, lane);
            uint32_t bh[4], bl[4];
            ldsm_x4(bh, bd_);
            ldsm_x4(bl, bd_ + (SM_W2L - SM_W2H));
            #pragma unroll
            for (int mt = 0; mt < 2; mt++) {
                mma_bf16(acc2[mt][2*p],   ah[mt], bh[0], bh[1]);
                mma_bf16(acc2[mt][2*p],   ah[mt], bl[0], bl[1]);
                mma_bf16(acc2[mt][2*p],   al[mt], bh[0], bh[1]);
                mma_bf16(acc2[mt][2*p+1], ah[mt], bh[2], bh[3]);
                mma_bf16(acc2[mt][2*p+1], ah[mt], bl[2], bl[3]);
                mma_bf16(acc2[mt][2*p+1], al[mt], bh[2], bh[3]);
            }
        }
    }
    #pragma unroll
    for (int mt = 0; mt < 2; mt++)
        #pragma unroll
        for (int nt = 0; nt < 4; nt++) {
            float* d = acc2[mt][nt];
            int c = nw2 + nt*8 + tig*2;
            int r1 = mw2 + mt*16 + gid;
            float b0f = bias2[c], b1f = bias2[c+1];
            size_t base0 = ((size_t)(b*64) + c) * HW + p0;
            size_t base1 = base0 + HW;
            fout[base0 + r1]     = d[0] + b0f + fin[base0 + r1];
            fout[base1 + r1]     = d[1] + b1f + fin[base1 + r1];
            fout[base0 + r1 + 8] = d[2] + b0f + fin[base0 + r1 + 8];
            fout[base1 + r1 + 8] = d[3] + b1f + fin[base1 + r1 + 8];
        }
}

// ---- K5: gather, 2 h-rows per iteration ----
#define GA_ST 136
#define GA_AH 0
#define GA_AL 17408
#define GA_BH 34816
#define GA_BL 52224
#define GA_SMEM 69632

__global__ void __launch_bounds__(256) k_gather() {
    extern __shared__ __align__(16) char smem[];
    uint32_t sb = smem_u32(smem);
    int b  = blockIdx.y;
    int l0 = blockIdx.x * 64;
    int tx = threadIdx.x;
    int lane = tx & 31, w = tx >> 5;
    int gid = lane >> 2, tig = lane & 3;
    int mw = (w & 3) * 16;
    int nw = (w >> 2) * 32;
    float acc[4][4];
    #pragma unroll
    for (int c = 0; c < 4; c++)
        #pragma unroll
        for (int d = 0; d < 4; d++) acc[c][d] = 0.0f;

    for (int h2 = 0; h2 < 32; h2++) {
        int h = h2 * 2;
        #pragma unroll
        for (int j = 0; j < 8; j++) {
            int r  = w + j * 8;
            int ww = lane * 2;
            int lg = b * L_ + l0 + r;
            float2 g = *(const float2*)&g_gxo[(size_t)lg*64 + ww];
            float gy0 = g_gyo[(size_t)lg*64 + h];
            float gy1 = g_gyo[(size_t)lg*64 + h + 1];
            uint32_t hi, lo;
            split2(gy0 * g.x, gy0 * g.y, hi, lo);
            uint32_t off = (uint32_t)(r * GA_ST + ww) * 2;
            sts32w(sb + GA_AH + off, hi);
            sts32w(sb + GA_AL + off, lo);
            split2(gy1 * g.x, gy1 * g.y, hi, lo);
            off = (uint32_t)(r * GA_ST + 64 + ww) * 2;
            sts32w(sb + GA_AH + off, hi);
            sts32w(sb + GA_AL + off, lo);
        }
        #pragma unroll
        for (int j = 0; j < 8; j++) {
            int r  = w + j * 8;
            int ww = lane * 2;
            const float* fr = &g_field2[((size_t)(b*64) + r)*HW + h*64];
            float2 g0 = *(const float2*)&fr[ww];
            float2 g1 = *(const float2*)&fr[64 + ww];
            uint32_t hi, lo;
            split2(g0.x, g0.y, hi, lo);
            uint32_t off = (uint32_t)(r * GA_ST + ww) * 2;
            sts32w(sb + GA_BH + off, hi);
            sts32w(sb + GA_BL + off, lo);
            split2(g1.x, g1.y, hi, lo);
            off = (uint32_t)(r * GA_ST + 64 + ww) * 2;
            sts32w(sb + GA_BH + off, hi);
            sts32w(sb + GA_BL + off, lo);
        }
        __syncthreads();
        #pragma unroll
        for (int ks = 0; ks < 8; ks++) {
            int k0 = ks * 16;
            uint32_t ah[4], al[4];
            uint32_t ad = lm_a_addr(sb + GA_AH, mw, k0, GA_ST, lane);
            ldsm_x4(ah, ad);
            ldsm_x4(al, ad + (GA_AL - GA_AH));
            #pragma unroll
            for (int p = 0; p < 2; p++) {
                uint32_t bd_ = lm_b4_addr(sb + GA_BH, nw + p*16, k0, GA_ST, lane);
                uint32_t bh[4], bl[4];
                ldsm_x4(bh, bd_);
                ldsm_x4(bl, bd_ + (GA_BL - GA_BH));
                mma_bf16(acc[2*p],   ah, bh[0], bh[1]);
                mma_bf16(acc[2*p],   ah, bl[0], bl[1]);
                mma_bf16(acc[2*p],   al, bh[0], bh[1]);
                mma_bf16(acc[2*p+1], ah, bh[2], bh[3]);
                mma_bf16(acc[2*p+1], ah, bl[2], bl[3]);
                mma_bf16(acc[2*p+1], al, bh[2], bh[3]);
            }
        }
        __syncthreads();
    }
    #pragma unroll
    for (int nt = 0; nt < 4; nt++) {
        float* d = acc[nt];
        int c = nw + nt*8 + tig*2;
        int r = mw + gid;
        size_t base0 = ((size_t)(b*L_) + l0 + r) * 64 + c;
        size_t base1 = ((size_t)(b*L_) + l0 + r + 8) * 64 + c;
        g_sampled[base0]     = d[0];
        g_sampled[base0 + 1] = d[1];
        g_sampled[base1]     = d[2];
        g_sampled[base1 + 1] = d[3];
    }
}

// ---- K6: tokens_out via mma.sync ----
#define KO_ST 72
#define KO_AH 0
#define KO_AL 9216
#define KO_BH 18432
#define KO_BL 27648

__global__ void __launch_bounds__(256)
k_out(const float* __restrict__ Wf, float* __restrict__ out) {
    __shared__ __align__(16) char smem[36864];
    uint32_t sb = smem_u32(smem);
    int m0 = blockIdx.x * 64;
    int e0 = blockIdx.y * 64;
    int tx = threadIdx.x;
    int lane = tx & 31, w = tx >> 5;
    int gid = lane >> 2, tig = lane & 3;
    int mw = (w & 3) * 16;
    int nw = (w >> 2) * 32;

    #pragma unroll
    for (int j = 0; j < 8; j++) {
        int r  = w + j * 8;
        int ww = lane * 2;
        float2 g = *(const float2*)&g_sampled[(size_t)(m0 + r)*64 + ww];
        uint32_t hi, lo; split2(g.x, g.y, hi, lo);
        uint32_t off = (uint32_t)(r * KO_ST + ww) * 2;
        sts32w(sb + KO_AH + off, hi);
        sts32w(sb + KO_AL + off, lo);
        float2 g2 = *(const float2*)&Wf[(size_t)(e0 + r)*64 + ww];
        split2(g2.x, g2.y, hi, lo);
        sts32w(sb + KO_BH + off, hi);
        sts32w(sb + KO_BL + off, lo);
    }
    __syncthreads();

    float acc[4][4];
    #pragma unroll
    for (int c = 0; c < 4; c++)
        #pragma unroll
        for (int d = 0; d < 4; d++) acc[c][d] = 0.0f;
    #pragma unroll
    for (int ks = 0; ks < 4; ks++) {
        int k0 = ks * 16;
        uint32_t ah[4], al[4];
        uint32_t ad = lm_a_addr(sb + KO_AH, mw, k0, KO_ST, lane);
        ldsm_x4(ah, ad);
        ldsm_x4(al, ad + (KO_AL - KO_AH));
        #pragma unroll
        for (int p = 0; p < 2; p++) {
            uint32_t bd_ = lm_b4_addr(sb + KO_BH, nw + p*16, k0, KO_ST, lane);
            uint32_t bh[4], bl[4];
            ldsm_x4(bh, bd_);
            ldsm_x4(bl, bd_ + (KO_BL - KO_BH));
            mma_bf16(acc[2*p],   ah, bh[0], bh[1]);
            mma_bf16(acc[2*p],   ah, bl[0], bl[1]);
            mma_bf16(acc[2*p],   al, bh[0], bh[1]);
            mma_bf16(acc[2*p+1], ah, bh[2], bh[3]);
            mma_bf16(acc[2*p+1], ah, bl[2], bl[3]);
            mma_bf16(acc[2*p+1], al, bh[2], bh[3]);
        }
    }
    #pragma unroll
    for (int nt = 0; nt < 4; nt++) {
        float* d = acc[nt];
        int e = e0 + nw + nt*8 + tig*2;
        int r = mw + gid;
        size_t base0 = (size_t)(m0 + r) * 512 + e;
        size_t base1 = (size_t)(m0 + r + 8) * 512 + e;
        out[base0]     = d[0];
        out[base0 + 1] = d[1];
        out[base1]     = d[2];
        out[base1 + 1] = d[3];
    }
}

// ------------------------------ launch -----------------------------------
extern "C" void kernel_launch(void* const* d_in, const int* in_sizes, int n_in,
                              void* d_out, int out_size) {
    const float* tokens     = (const float*)d_in[0];
    const float* positions  = (const float*)d_in[1];
    const float* W_to_field = (const float*)d_in[2];
    const float* W_from_field = (const float*)d_in[3];
    const float* conv1_w    = (const float*)d_in[4];
    const float* conv1_b    = (const float*)d_in[5];
    const float* conv2_w    = (const float*)d_in[6];
    const float* conv2_b    = (const float*)d_in[7];
    const float* log_sigma  = (const float*)d_in[8];
    float* out = (float*)d_out;

    cudaFuncSetAttribute(k_step, cudaFuncAttributeMaxDynamicSharedMemorySize,
                         STEP_SMEM);
    cudaFuncSetAttribute(k_gather, cudaFuncAttributeMaxDynamicSharedMemorySize,
                         GA_SMEM);

    k_split_w<<<288, 256>>>(conv1_w, conv2_w);
    k_gauss<<<B_*L_, 64>>>(positions, log_sigma);
    k_proj<<<(B_*L_)/64, 256>>>(tokens, W_to_field);
    k_scatter<<<dim3(32, B_), 256>>>();
    for (int s = 0; s < STEPS_; s++) {
        k_step<<<dim3(32, B_), 256, STEP_SMEM>>>(conv1_b, conv2_b, s & 1);
    }
    k_gather<<<dim3(32, B_), 256, GA_SMEM>>>();
    k_out<<<dim3((B_*L_)/64, 8), 256>>>(W_from_field, out);
}